// round 1
// baseline (speedup 1.0000x reference)
#include <cuda_runtime.h>

// AFT-Full, algebraically simplified:
//   exp_pos_bias == all-ones  =>  num/den are per-(b,d) sums over t, independent of i.
//   out = ( sigmoid(q@WqT) * (sum_t exp(K-maxK)*V) / (sum_t exp(K-maxK)) ) @ WoT
// where maxK[t,d] = max over batch of K[b,t,d].
//
// Inputs (metadata order): q, k, v, Wq, Wk, Wv, Wo, W_bias (W_bias unused).

#define BB 4
#define TT 2048
#define DD 1024
#define MTOT (BB * TT)   // 8192
#define KDIM 1024
#define NDIM 1024

// Scratch (static device globals; no runtime allocation)
__device__ float g_Kp[MTOT * DD];
__device__ float g_Vp[MTOT * DD];
__device__ float g_Yt[MTOT * DD];
__device__ float g_num[BB * DD];
__device__ float g_den[BB * DD];

// ---------------------------------------------------------------------------
// zero-init num/den accumulators
// ---------------------------------------------------------------------------
__global__ void init_numden() {
    int i = blockIdx.x * blockDim.x + threadIdx.x;
    if (i < BB * DD) {
        g_num[i] = 0.0f;
        g_den[i] = 0.0f;
    }
}

// ---------------------------------------------------------------------------
// Tiled SGEMM: C[M,N] = A[M,K] @ B[N,K]^T   (both operands K-contiguous)
// M=8192, N=1024, K=1024 fixed. BM=BN=128, BK=8, 256 threads, 8x8 per thread.
// MODE: 0 -> C=g_Kp, 1 -> C=g_Vp, 2 -> C=g_Yt with sigmoid*num/den epilogue,
//       3 -> A=g_Yt, C=Cout (final output projection)
// ---------------------------------------------------------------------------
template <int MODE>
__global__ __launch_bounds__(256) void sgemm_kernel(
    const float* __restrict__ Ain,
    const float* __restrict__ Bw,
    float* __restrict__ Cout)
{
    constexpr int BM = 128, BN = 128, BK = 8;

    const float* A;
    float* C;
    if (MODE == 0)      { A = Ain;  C = g_Kp;  }
    else if (MODE == 1) { A = Ain;  C = g_Vp;  }
    else if (MODE == 2) { A = Ain;  C = g_Yt;  }
    else                { A = g_Yt; C = Cout;  }

    __shared__ float As[BK][BM];
    __shared__ float Bs[BK][BN];

    const int tid = threadIdx.x;
    const int loadRow = tid >> 1;         // 0..127
    const int loadCol = (tid & 1) << 2;   // 0 or 4

    const int rowBase = blockIdx.y * BM;
    const int colBase = blockIdx.x * BN;

    const float* Aptr = A  + (size_t)(rowBase + loadRow) * KDIM + loadCol;
    const float* Bptr = Bw + (size_t)(colBase + loadRow) * KDIM + loadCol;

    const int ty = tid >> 4;   // 0..15
    const int tx = tid & 15;   // 0..15

    float acc[8][8];
#pragma unroll
    for (int i = 0; i < 8; i++)
#pragma unroll
        for (int j = 0; j < 8; j++) acc[i][j] = 0.0f;

    for (int k0 = 0; k0 < KDIM; k0 += BK) {
        float4 a4 = *(const float4*)(Aptr + k0);
        float4 b4 = *(const float4*)(Bptr + k0);

        __syncthreads();
        As[loadCol + 0][loadRow] = a4.x;
        As[loadCol + 1][loadRow] = a4.y;
        As[loadCol + 2][loadRow] = a4.z;
        As[loadCol + 3][loadRow] = a4.w;
        Bs[loadCol + 0][loadRow] = b4.x;
        Bs[loadCol + 1][loadRow] = b4.y;
        Bs[loadCol + 2][loadRow] = b4.z;
        Bs[loadCol + 3][loadRow] = b4.w;
        __syncthreads();

#pragma unroll
        for (int kk = 0; kk < BK; kk++) {
            float a[8], b[8];
            *(float4*)(a)     = *(const float4*)&As[kk][ty * 8];
            *(float4*)(a + 4) = *(const float4*)&As[kk][ty * 8 + 4];
            *(float4*)(b)     = *(const float4*)&Bs[kk][tx * 8];
            *(float4*)(b + 4) = *(const float4*)&Bs[kk][tx * 8 + 4];
#pragma unroll
            for (int i = 0; i < 8; i++)
#pragma unroll
                for (int j = 0; j < 8; j++)
                    acc[i][j] = fmaf(a[i], b[j], acc[i][j]);
        }
    }

    const int row0 = rowBase + ty * 8;
    const int col0 = colBase + tx * 8;

#pragma unroll
    for (int i = 0; i < 8; i++) {
        const int row = row0 + i;
        float* crow = C + (size_t)row * NDIM + col0;
        if (MODE == 2) {
            const int b = row >> 11;  // row / 2048
            const float* nump = g_num + b * DD + col0;
            const float* denp = g_den + b * DD + col0;
#pragma unroll
            for (int j4 = 0; j4 < 8; j4 += 4) {
                float4 out;
                float* o = (float*)&out;
#pragma unroll
                for (int j = 0; j < 4; j++) {
                    float x = acc[i][j4 + j];
                    float sig = 1.0f / (1.0f + __expf(-x));
                    o[j] = sig * nump[j4 + j] / denp[j4 + j];
                }
                *(float4*)(crow + j4) = out;
            }
        } else {
#pragma unroll
            for (int j4 = 0; j4 < 8; j4 += 4) {
                float4 out;
                out.x = acc[i][j4 + 0];
                out.y = acc[i][j4 + 1];
                out.z = acc[i][j4 + 2];
                out.w = acc[i][j4 + 3];
                *(float4*)(crow + j4) = out;
            }
        }
    }
}

// ---------------------------------------------------------------------------
// Reduction: for each (b,d):
//   m[t,d]  = max_b Kp[b,t,d]
//   num[b,d] += sum_t exp(Kp[b,t,d]-m)*Vp[b,t,d]
//   den[b,d] += sum_t exp(Kp[b,t,d]-m)
// grid = (DD/128, TT/128); block = 128 threads (one d-lane each, 128 t's).
// Coalesced across d; partial sums combined via atomicAdd.
// ---------------------------------------------------------------------------
__global__ __launch_bounds__(128) void reduce_kernel() {
    const int d  = blockIdx.x * 128 + threadIdx.x;
    const int t0 = blockIdx.y * 128;

    float num0 = 0.f, num1 = 0.f, num2 = 0.f, num3 = 0.f;
    float den0 = 0.f, den1 = 0.f, den2 = 0.f, den3 = 0.f;

    for (int t = t0; t < t0 + 128; t++) {
        const size_t off = (size_t)t * DD + d;
        float k0 = g_Kp[off + (size_t)0 * TT * DD];
        float k1 = g_Kp[off + (size_t)1 * TT * DD];
        float k2 = g_Kp[off + (size_t)2 * TT * DD];
        float k3 = g_Kp[off + (size_t)3 * TT * DD];
        float m = fmaxf(fmaxf(k0, k1), fmaxf(k2, k3));
        float e0 = __expf(k0 - m);
        float e1 = __expf(k1 - m);
        float e2 = __expf(k2 - m);
        float e3 = __expf(k3 - m);
        float v0 = g_Vp[off + (size_t)0 * TT * DD];
        float v1 = g_Vp[off + (size_t)1 * TT * DD];
        float v2 = g_Vp[off + (size_t)2 * TT * DD];
        float v3 = g_Vp[off + (size_t)3 * TT * DD];
        num0 = fmaf(e0, v0, num0);  den0 += e0;
        num1 = fmaf(e1, v1, num1);  den1 += e1;
        num2 = fmaf(e2, v2, num2);  den2 += e2;
        num3 = fmaf(e3, v3, num3);  den3 += e3;
    }

    atomicAdd(&g_num[0 * DD + d], num0);
    atomicAdd(&g_num[1 * DD + d], num1);
    atomicAdd(&g_num[2 * DD + d], num2);
    atomicAdd(&g_num[3 * DD + d], num3);
    atomicAdd(&g_den[0 * DD + d], den0);
    atomicAdd(&g_den[1 * DD + d], den1);
    atomicAdd(&g_den[2 * DD + d], den2);
    atomicAdd(&g_den[3 * DD + d], den3);
}

// ---------------------------------------------------------------------------
extern "C" void kernel_launch(void* const* d_in, const int* in_sizes, int n_in,
                              void* d_out, int out_size) {
    const float* q  = (const float*)d_in[0];
    const float* k  = (const float*)d_in[1];
    const float* v  = (const float*)d_in[2];
    const float* Wq = (const float*)d_in[3];
    const float* Wk = (const float*)d_in[4];
    const float* Wv = (const float*)d_in[5];
    const float* Wo = (const float*)d_in[6];
    // d_in[7] = W_bias: provably unused (exp(pos_bias - pos_bias) == 1)

    float* out = (float*)d_out;

    dim3 gemmGrid(NDIM / 128, MTOT / 128);  // (8, 64)
    dim3 gemmBlock(256);

    // K and V projections
    sgemm_kernel<0><<<gemmGrid, gemmBlock>>>(k, Wk, nullptr);
    sgemm_kernel<1><<<gemmGrid, gemmBlock>>>(v, Wv, nullptr);

    // num/den reduction
    init_numden<<<(BB * DD + 255) / 256, 256>>>();
    dim3 redGrid(DD / 128, TT / 128);       // (8, 16)
    reduce_kernel<<<redGrid, 128>>>();

    // Q projection fused with sigmoid * num / den -> Yt
    sgemm_kernel<2><<<gemmGrid, gemmBlock>>>(q, Wq, nullptr);

    // Output projection: out = Yt @ Wo^T
    sgemm_kernel<3><<<gemmGrid, gemmBlock>>>(nullptr, Wo, out);
}

// round 2
// speedup vs baseline: 2.0709x; 2.0709x over previous
#include <cuda_runtime.h>
#include <cuda_bf16.h>
#include <cstdint>

// AFT-Full simplified: exp_pos_bias == 1  =>  num/den are per-(b,d) sums over t.
// out = ( sigmoid(q@WqT) * num/den ) @ WoT,
//   num[b,d] = sum_t exp(Kp[b,t,d]-m[t,d])*Vp[b,t,d],  den = sum_t exp(Kp-m),
//   m[t,d] = max_b Kp[b,t,d]   (does NOT cancel: varies with t)
//
// GEMMs run on tensor cores: bf16 hi/lo split (3 MMAs) for ~fp32 accuracy.

#define BB 4
#define TT 2048
#define DD 1024
#define MTOT (BB * TT)   // 8192
#define KD 1024

using bf16 = __nv_bfloat16;

// ---------------- scratch (static device globals) ----------------
__device__ bf16 g_qhi[MTOT * KD], g_qlo[MTOT * KD];
__device__ bf16 g_khi[MTOT * KD], g_klo[MTOT * KD];
__device__ bf16 g_vhi[MTOT * KD], g_vlo[MTOT * KD];
__device__ bf16 g_Wqhi[DD * KD], g_Wqlo[DD * KD];
__device__ bf16 g_Wkhi[DD * KD], g_Wklo[DD * KD];
__device__ bf16 g_Wvhi[DD * KD], g_Wvlo[DD * KD];
__device__ bf16 g_Wohi[DD * KD], g_Wolo[DD * KD];
__device__ bf16 g_Ythi[MTOT * DD], g_Ytlo[MTOT * DD];
__device__ float g_Kp[MTOT * DD];
__device__ float g_Vp[MTOT * DD];
__device__ float g_num[BB * DD];
__device__ float g_den[BB * DD];

// ---------------- fp32 -> bf16 hi/lo split ----------------
__global__ __launch_bounds__(256) void convert_split(
    const float* __restrict__ src, bf16* __restrict__ hi, bf16* __restrict__ lo, int n4)
{
    int i = blockIdx.x * blockDim.x + threadIdx.x;
    if (i >= n4) return;
    float4 x = ((const float4*)src)[i];
    bf16 h0 = __float2bfloat16(x.x);
    bf16 h1 = __float2bfloat16(x.y);
    bf16 h2 = __float2bfloat16(x.z);
    bf16 h3 = __float2bfloat16(x.w);
    bf16 l0 = __float2bfloat16(x.x - __bfloat162float(h0));
    bf16 l1 = __float2bfloat16(x.y - __bfloat162float(h1));
    bf16 l2 = __float2bfloat16(x.z - __bfloat162float(h2));
    bf16 l3 = __float2bfloat16(x.w - __bfloat162float(h3));
    __nv_bfloat162* hp = (__nv_bfloat162*)(hi + i * 4);
    __nv_bfloat162* lp = (__nv_bfloat162*)(lo + i * 4);
    hp[0] = __nv_bfloat162(h0, h1);
    hp[1] = __nv_bfloat162(h2, h3);
    lp[0] = __nv_bfloat162(l0, l1);
    lp[1] = __nv_bfloat162(l2, l3);
}

__global__ void init_numden() {
    int i = blockIdx.x * blockDim.x + threadIdx.x;
    if (i < BB * DD) { g_num[i] = 0.0f; g_den[i] = 0.0f; }
}

// ---------------- ldmatrix / mma wrappers ----------------
__device__ __forceinline__ void ldsm_x4(uint32_t& r0, uint32_t& r1, uint32_t& r2, uint32_t& r3, uint32_t addr) {
    asm volatile("ldmatrix.sync.aligned.m8n8.x4.shared.b16 {%0,%1,%2,%3}, [%4];"
                 : "=r"(r0), "=r"(r1), "=r"(r2), "=r"(r3) : "r"(addr));
}
__device__ __forceinline__ void mma_bf16(float* d, const uint32_t* a, const uint32_t* b) {
    asm volatile("mma.sync.aligned.m16n8k16.row.col.f32.bf16.bf16.f32 "
                 "{%0,%1,%2,%3}, {%4,%5,%6,%7}, {%8,%9}, {%0,%1,%2,%3};"
                 : "+f"(d[0]), "+f"(d[1]), "+f"(d[2]), "+f"(d[3])
                 : "r"(a[0]), "r"(a[1]), "r"(a[2]), "r"(a[3]), "r"(b[0]), "r"(b[1]));
}

// ---------------- tensor-core GEMM: C[M,N] = A[M,K] @ B[N,K]^T ----------------
// M=8192, N=1024, K=1024. BM=BN=128, BK=16, 256 threads (8 warps, 2x4).
// MODE 0: C = g_Kp (fp32). 1: C = g_Vp. 2: Yt = sigmoid(acc)*num/den -> hi/lo.
// MODE 3: A = g_Yt(hi/lo), C = Cout (fp32 final output).
template <int MODE>
__global__ __launch_bounds__(256) void mma_gemm(
    const bf16* __restrict__ Ahi_, const bf16* __restrict__ Alo_,
    const bf16* __restrict__ Bhi,  const bf16* __restrict__ Blo,
    float* __restrict__ Cout)
{
    constexpr int BM = 128, BN = 128, BK = 16;
    constexpr int LDS = BK + 8;  // 24 bf16 (48B) row stride -> conflict-free ldmatrix

    const bf16* Ahi = (MODE == 3) ? g_Ythi : Ahi_;
    const bf16* Alo = (MODE == 3) ? g_Ytlo : Alo_;

    __shared__ bf16 sAhi[BM * LDS], sAlo[BM * LDS];
    __shared__ bf16 sBhi[BN * LDS], sBlo[BN * LDS];

    const int tid = threadIdx.x;
    const int wid = tid >> 5, lane = tid & 31;
    const int rowBase = blockIdx.y * BM;
    const int colBase = blockIdx.x * BN;

    // global->smem staging: 128 rows x 16 cols bf16 = 2 chunks of 8 bf16 per row
    const int ldRow = tid >> 1;           // 0..127
    const int ldCol = (tid & 1) * 8;      // 0 or 8
    const size_t aOff = (size_t)(rowBase + ldRow) * KD + ldCol;
    const size_t bOff = (size_t)(colBase + ldRow) * KD + ldCol;
    const int sOff = ldRow * LDS + ldCol;

    // warp tiling: 2 (M) x 4 (N); warp tile 64x32
    const int warpM = (wid >> 2) * 64;
    const int warpN = (wid & 3) * 32;

    const uint32_t baseAhi = (uint32_t)__cvta_generic_to_shared(sAhi);
    const uint32_t baseAlo = (uint32_t)__cvta_generic_to_shared(sAlo);
    const uint32_t baseBhi = (uint32_t)__cvta_generic_to_shared(sBhi);
    const uint32_t baseBlo = (uint32_t)__cvta_generic_to_shared(sBlo);

    // ldmatrix addresses (bf16 units -> *2 bytes)
    const int aRow = warpM + (lane & 15);
    const int aCol = (lane >> 4) * 8;
    const int bRow = warpN + ((lane >> 4) << 3) + (lane & 7);
    const int bCol = ((lane >> 3) & 1) * 8;

    float acc[4][4][4];
#pragma unroll
    for (int m = 0; m < 4; m++)
#pragma unroll
        for (int n = 0; n < 4; n++)
#pragma unroll
            for (int r = 0; r < 4; r++) acc[m][n][r] = 0.0f;

    uint4 stAh = *(const uint4*)(Ahi + aOff);
    uint4 stAl = *(const uint4*)(Alo + aOff);
    uint4 stBh = *(const uint4*)(Bhi + bOff);
    uint4 stBl = *(const uint4*)(Blo + bOff);

    for (int kt = 0; kt < KD / BK; kt++) {
        *(uint4*)(sAhi + sOff) = stAh;
        *(uint4*)(sAlo + sOff) = stAl;
        *(uint4*)(sBhi + sOff) = stBh;
        *(uint4*)(sBlo + sOff) = stBl;
        __syncthreads();

        if (kt < KD / BK - 1) {
            const size_t o = (size_t)(kt + 1) * BK;
            stAh = *(const uint4*)(Ahi + aOff + o);
            stAl = *(const uint4*)(Alo + aOff + o);
            stBh = *(const uint4*)(Bhi + bOff + o);
            stBl = *(const uint4*)(Blo + bOff + o);
        }

        uint32_t a_hi[4][4], a_lo[4][4], b_hi[4][2], b_lo[4][2];
#pragma unroll
        for (int mf = 0; mf < 4; mf++) {
            uint32_t addr = (uint32_t)(((aRow + mf * 16) * LDS + aCol) * 2);
            ldsm_x4(a_hi[mf][0], a_hi[mf][1], a_hi[mf][2], a_hi[mf][3], baseAhi + addr);
            ldsm_x4(a_lo[mf][0], a_lo[mf][1], a_lo[mf][2], a_lo[mf][3], baseAlo + addr);
        }
#pragma unroll
        for (int p = 0; p < 2; p++) {
            uint32_t addr = (uint32_t)(((bRow + p * 16) * LDS + bCol) * 2);
            ldsm_x4(b_hi[2 * p][0], b_hi[2 * p][1], b_hi[2 * p + 1][0], b_hi[2 * p + 1][1], baseBhi + addr);
            ldsm_x4(b_lo[2 * p][0], b_lo[2 * p][1], b_lo[2 * p + 1][0], b_lo[2 * p + 1][1], baseBlo + addr);
        }

#pragma unroll
        for (int m = 0; m < 4; m++)
#pragma unroll
            for (int n = 0; n < 4; n++) {
                mma_bf16(acc[m][n], a_hi[m], b_hi[n]);
                mma_bf16(acc[m][n], a_hi[m], b_lo[n]);
                mma_bf16(acc[m][n], a_lo[m], b_hi[n]);
            }
        __syncthreads();
    }

    // ---------------- epilogue ----------------
    const int er = rowBase + warpM + (lane >> 2);
    const int ec = colBase + warpN + (lane & 3) * 2;

    if (MODE == 2) {
        const int b = rowBase >> 11;  // whole 128-row tile in one batch
        float nd[4][2];
#pragma unroll
        for (int n = 0; n < 4; n++) {
            int c = ec + n * 8;
            nd[n][0] = g_num[b * DD + c]     / g_den[b * DD + c];
            nd[n][1] = g_num[b * DD + c + 1] / g_den[b * DD + c + 1];
        }
#pragma unroll
        for (int m = 0; m < 4; m++)
#pragma unroll
            for (int n = 0; n < 4; n++) {
                int c = ec + n * 8;
#pragma unroll
                for (int half = 0; half < 2; half++) {
                    int r = er + m * 16 + half * 8;
                    float y0 = nd[n][0] / (1.0f + __expf(-acc[m][n][half * 2]));
                    float y1 = nd[n][1] / (1.0f + __expf(-acc[m][n][half * 2 + 1]));
                    bf16 h0 = __float2bfloat16(y0);
                    bf16 h1 = __float2bfloat16(y1);
                    bf16 l0 = __float2bfloat16(y0 - __bfloat162float(h0));
                    bf16 l1 = __float2bfloat16(y1 - __bfloat162float(h1));
                    *(__nv_bfloat162*)(g_Ythi + (size_t)r * DD + c) = __nv_bfloat162(h0, h1);
                    *(__nv_bfloat162*)(g_Ytlo + (size_t)r * DD + c) = __nv_bfloat162(l0, l1);
                }
            }
    } else {
        float* C = (MODE == 0) ? g_Kp : (MODE == 1) ? g_Vp : Cout;
#pragma unroll
        for (int m = 0; m < 4; m++)
#pragma unroll
            for (int n = 0; n < 4; n++) {
                int c = ec + n * 8;
#pragma unroll
                for (int half = 0; half < 2; half++) {
                    int r = er + m * 16 + half * 8;
                    *(float2*)(C + (size_t)r * DD + c) =
                        make_float2(acc[m][n][half * 2], acc[m][n][half * 2 + 1]);
                }
            }
    }
}

// ---------------- num/den reduction ----------------
// grid = (DD/128, TT/16) = (8, 128) -> 1024 blocks; each block: 16 t's, 128 d's
__global__ __launch_bounds__(128) void reduce_kernel() {
    const int d  = blockIdx.x * 128 + threadIdx.x;
    const int t0 = blockIdx.y * 16;

    float num0 = 0.f, num1 = 0.f, num2 = 0.f, num3 = 0.f;
    float den0 = 0.f, den1 = 0.f, den2 = 0.f, den3 = 0.f;

#pragma unroll 4
    for (int t = t0; t < t0 + 16; t++) {
        const size_t off = (size_t)t * DD + d;
        float k0 = g_Kp[off + (size_t)0 * TT * DD];
        float k1 = g_Kp[off + (size_t)1 * TT * DD];
        float k2 = g_Kp[off + (size_t)2 * TT * DD];
        float k3 = g_Kp[off + (size_t)3 * TT * DD];
        float m = fmaxf(fmaxf(k0, k1), fmaxf(k2, k3));
        float e0 = __expf(k0 - m);
        float e1 = __expf(k1 - m);
        float e2 = __expf(k2 - m);
        float e3 = __expf(k3 - m);
        float v0 = g_Vp[off + (size_t)0 * TT * DD];
        float v1 = g_Vp[off + (size_t)1 * TT * DD];
        float v2 = g_Vp[off + (size_t)2 * TT * DD];
        float v3 = g_Vp[off + (size_t)3 * TT * DD];
        num0 = fmaf(e0, v0, num0);  den0 += e0;
        num1 = fmaf(e1, v1, num1);  den1 += e1;
        num2 = fmaf(e2, v2, num2);  den2 += e2;
        num3 = fmaf(e3, v3, num3);  den3 += e3;
    }

    atomicAdd(&g_num[0 * DD + d], num0);
    atomicAdd(&g_num[1 * DD + d], num1);
    atomicAdd(&g_num[2 * DD + d], num2);
    atomicAdd(&g_num[3 * DD + d], num3);
    atomicAdd(&g_den[0 * DD + d], den0);
    atomicAdd(&g_den[1 * DD + d], den1);
    atomicAdd(&g_den[2 * DD + d], den2);
    atomicAdd(&g_den[3 * DD + d], den3);
}

// ---------------------------------------------------------------------------
extern "C" void kernel_launch(void* const* d_in, const int* in_sizes, int n_in,
                              void* d_out, int out_size) {
    const float* q  = (const float*)d_in[0];
    const float* k  = (const float*)d_in[1];
    const float* v  = (const float*)d_in[2];
    const float* Wq = (const float*)d_in[3];
    const float* Wk = (const float*)d_in[4];
    const float* Wv = (const float*)d_in[5];
    const float* Wv_o = (const float*)d_in[6];
    // d_in[7] = W_bias: provably unused (exp(pos_bias - pos_bias) == 1)
    float* out = (float*)d_out;

    bf16 *qhi, *qlo, *khi, *klo, *vhi, *vlo;
    bf16 *wqh, *wql, *wkh, *wkl, *wvh, *wvl, *woh, *wol;
    cudaGetSymbolAddress((void**)&qhi, g_qhi);  cudaGetSymbolAddress((void**)&qlo, g_qlo);
    cudaGetSymbolAddress((void**)&khi, g_khi);  cudaGetSymbolAddress((void**)&klo, g_klo);
    cudaGetSymbolAddress((void**)&vhi, g_vhi);  cudaGetSymbolAddress((void**)&vlo, g_vlo);
    cudaGetSymbolAddress((void**)&wqh, g_Wqhi); cudaGetSymbolAddress((void**)&wql, g_Wqlo);
    cudaGetSymbolAddress((void**)&wkh, g_Wkhi); cudaGetSymbolAddress((void**)&wkl, g_Wklo);
    cudaGetSymbolAddress((void**)&wvh, g_Wvhi); cudaGetSymbolAddress((void**)&wvl, g_Wvlo);
    cudaGetSymbolAddress((void**)&woh, g_Wohi); cudaGetSymbolAddress((void**)&wol, g_Wolo);

    const int nBig = MTOT * KD / 4;   // float4 count for q/k/v
    const int nW   = DD * KD / 4;
    convert_split<<<(nBig + 255) / 256, 256>>>(q, qhi, qlo, nBig);
    convert_split<<<(nBig + 255) / 256, 256>>>(k, khi, klo, nBig);
    convert_split<<<(nBig + 255) / 256, 256>>>(v, vhi, vlo, nBig);
    convert_split<<<(nW + 255) / 256, 256>>>(Wq,   wqh, wql, nW);
    convert_split<<<(nW + 255) / 256, 256>>>(Wk,   wkh, wkl, nW);
    convert_split<<<(nW + 255) / 256, 256>>>(Wv,   wvh, wvl, nW);
    convert_split<<<(nW + 255) / 256, 256>>>(Wv_o, woh, wol, nW);

    dim3 gemmGrid(DD / 128, MTOT / 128);  // (8, 64)

    // K, V projections (tensor core)
    mma_gemm<0><<<gemmGrid, 256>>>(khi, klo, wkh, wkl, nullptr);
    mma_gemm<1><<<gemmGrid, 256>>>(vhi, vlo, wvh, wvl, nullptr);

    // num/den
    init_numden<<<(BB * DD + 255) / 256, 256>>>();
    dim3 redGrid(DD / 128, TT / 16);      // (8, 128)
    reduce_kernel<<<redGrid, 128>>>();

    // Q projection fused with sigmoid*num/den -> Yt (bf16 hi/lo)
    mma_gemm<2><<<gemmGrid, 256>>>(qhi, qlo, wqh, wql, nullptr);

    // out = Yt @ Wo^T
    mma_gemm<3><<<gemmGrid, 256>>>(nullptr, nullptr, woh, wol, out);
}

// round 4
// speedup vs baseline: 2.3988x; 1.1583x over previous
#include <cuda_runtime.h>
#include <cuda_bf16.h>
#include <cstdint>

// AFT-Full simplified: exp_pos_bias == 1  =>  num/den are per-(b,d) sums over t.
// out = ( sigmoid(q@WqT) * num/den ) @ WoT
//   num[b,d] = sum_t exp(Kp[b,t,d]-m[t,d])*Vp[b,t,d],  den = sum_t exp(Kp-m),
//   m[t,d] = max_b Kp[b,t,d]
// GEMMs: mma.sync bf16 (tcgen05 PTX rejected at compute_103 target), 3-term
// hi/lo split for fp32-class accuracy, cp.async 3-stage pipeline.

#define BB 4
#define TT 2048
#define DD 1024
#define MTOT (BB * TT)   // 8192
#define KD 1024

using bf16 = __nv_bfloat16;

// ---------------- scratch (static device globals) ----------------
__device__ bf16 g_qhi[MTOT * KD], g_qlo[MTOT * KD];
__device__ bf16 g_khi[MTOT * KD], g_klo[MTOT * KD];
__device__ bf16 g_vhi[MTOT * KD], g_vlo[MTOT * KD];
__device__ bf16 g_Wqhi[DD * KD], g_Wqlo[DD * KD];
__device__ bf16 g_Wkhi[DD * KD], g_Wklo[DD * KD];
__device__ bf16 g_Wvhi[DD * KD], g_Wvlo[DD * KD];
__device__ bf16 g_Wohi[DD * KD], g_Wolo[DD * KD];
__device__ bf16 g_Ythi[MTOT * DD], g_Ytlo[MTOT * DD];
__device__ float g_Kp[MTOT * DD];
__device__ float g_Vp[MTOT * DD];
__device__ float g_num[BB * DD];
__device__ float g_den[BB * DD];

// ---------------- fp32 -> bf16 hi/lo split ----------------
__global__ __launch_bounds__(256) void convert_split(
    const float* __restrict__ src, bf16* __restrict__ hi, bf16* __restrict__ lo, int n4)
{
    int i = blockIdx.x * blockDim.x + threadIdx.x;
    if (i >= n4) return;
    float4 x = ((const float4*)src)[i];
    bf16 h0 = __float2bfloat16(x.x);
    bf16 h1 = __float2bfloat16(x.y);
    bf16 h2 = __float2bfloat16(x.z);
    bf16 h3 = __float2bfloat16(x.w);
    bf16 l0 = __float2bfloat16(x.x - __bfloat162float(h0));
    bf16 l1 = __float2bfloat16(x.y - __bfloat162float(h1));
    bf16 l2 = __float2bfloat16(x.z - __bfloat162float(h2));
    bf16 l3 = __float2bfloat16(x.w - __bfloat162float(h3));
    __nv_bfloat162* hp = (__nv_bfloat162*)(hi + i * 4);
    __nv_bfloat162* lp = (__nv_bfloat162*)(lo + i * 4);
    hp[0] = __nv_bfloat162(h0, h1);
    hp[1] = __nv_bfloat162(h2, h3);
    lp[0] = __nv_bfloat162(l0, l1);
    lp[1] = __nv_bfloat162(l2, l3);
}

__global__ void init_numden() {
    int i = blockIdx.x * blockDim.x + threadIdx.x;
    if (i < BB * DD) { g_num[i] = 0.0f; g_den[i] = 0.0f; }
}

// ---------------- PTX helpers ----------------
__device__ __forceinline__ void ldsm_x4(uint32_t& r0, uint32_t& r1, uint32_t& r2, uint32_t& r3, uint32_t addr) {
    asm volatile("ldmatrix.sync.aligned.m8n8.x4.shared.b16 {%0,%1,%2,%3}, [%4];"
                 : "=r"(r0), "=r"(r1), "=r"(r2), "=r"(r3) : "r"(addr));
}
__device__ __forceinline__ void mma_bf16(float* d, const uint32_t* a, const uint32_t* b) {
    asm volatile("mma.sync.aligned.m16n8k16.row.col.f32.bf16.bf16.f32 "
                 "{%0,%1,%2,%3}, {%4,%5,%6,%7}, {%8,%9}, {%0,%1,%2,%3};"
                 : "+f"(d[0]), "+f"(d[1]), "+f"(d[2]), "+f"(d[3])
                 : "r"(a[0]), "r"(a[1]), "r"(a[2]), "r"(a[3]), "r"(b[0]), "r"(b[1]));
}
__device__ __forceinline__ void cp16(uint32_t s, const void* g) {
    asm volatile("cp.async.cg.shared.global [%0], [%1], 16;" :: "r"(s), "l"(g));
}
__device__ __forceinline__ void cp_commit() {
    asm volatile("cp.async.commit_group;" ::: "memory");
}
template <int N>
__device__ __forceinline__ void cp_wait() {
    asm volatile("cp.async.wait_group %0;" :: "n"(N) : "memory");
}

// ---------------- tensor-core GEMM: C[M,N] = A[M,K] @ B[N,K]^T ----------------
// M=8192, N=1024, K=1024. BM=BN=128, BK=32, 3-stage cp.async pipeline,
// 256 threads (8 warps 2x4, warp tile 64x32). 3 MMAs per k16 (hi/lo split).
// MODE 0: C=g_Kp  1: C=g_Vp  2: Yt=sigmoid(acc)*num/den -> hi/lo  3: A=Yt, C=Cout
constexpr int BK = 32;
constexpr int NT = KD / BK;            // 32 k-tiles
constexpr int LDS = BK + 8;            // 40 bf16 = 80 B row stride (conflict-free)
constexpr int TILE_B = 128 * LDS * 2;  // 10240 B per array
constexpr int STAGE_B = 4 * TILE_B;    // 40960 B per stage (Ahi,Alo,Bhi,Blo)
constexpr int NSTAGE = 3;
constexpr int SMEM_TOTAL = NSTAGE * STAGE_B;  // 122880 B

template <int MODE>
__global__ __launch_bounds__(256, 1) void mma_gemm(
    const bf16* __restrict__ Ahi_, const bf16* __restrict__ Alo_,
    const bf16* __restrict__ Bhi,  const bf16* __restrict__ Blo,
    float* __restrict__ Cout)
{
    extern __shared__ char smem[];
    const uint32_t sb = (uint32_t)__cvta_generic_to_shared(smem);

    const bf16* Ahi = (MODE == 3) ? g_Ythi : Ahi_;
    const bf16* Alo = (MODE == 3) ? g_Ytlo : Alo_;

    const int tid = threadIdx.x;
    const int wid = tid >> 5, lane = tid & 31;
    const int rowBase = blockIdx.y * 128;
    const int colBase = blockIdx.x * 128;

    // warp tiling: 2 (M) x 4 (N); warp tile 64x32
    const int warpM = (wid >> 2) * 64;
    const int warpN = (wid & 3) * 32;

    // cp.async chunk mapping: 512 chunks (16B) per 128x32 array; 2 per thread
    const int ldRow = tid >> 1;                 // 0..127 (paired with c below)
    // chunk ch = tid + i*256: row = ch>>2, c = ch&3
    // ldmatrix lane addressing (within 128-row tile, bf16 units)
    const int aRowL = warpM + (lane & 15);
    const int aColL = (lane >> 4) * 8;
    const int bRowL = warpN + ((lane >> 4) << 3) + (lane & 7);
    const int bColL = ((lane >> 3) & 1) * 8;

    float acc[4][4][4];
#pragma unroll
    for (int m = 0; m < 4; m++)
#pragma unroll
        for (int n = 0; n < 4; n++)
#pragma unroll
            for (int r = 0; r < 4; r++) acc[m][n][r] = 0.0f;

    auto fill_stage = [&](int buf, int k0) {
        const uint32_t stg = sb + buf * STAGE_B;
#pragma unroll
        for (int i = 0; i < 2; i++) {
            const int ch = tid + i * 256;
            const int r = ch >> 2, c = ch & 3;
            const uint32_t so = (uint32_t)(r * (LDS * 2) + c * 16);
            const size_t gA = (size_t)(rowBase + r) * KD + k0 + c * 8;
            const size_t gB = (size_t)(colBase + r) * KD + k0 + c * 8;
            cp16(stg + so,               Ahi + gA);
            cp16(stg + TILE_B + so,      Alo + gA);
            cp16(stg + 2 * TILE_B + so,  Bhi + gB);
            cp16(stg + 3 * TILE_B + so,  Blo + gB);
        }
        cp_commit();
    };

    fill_stage(0, 0);
    fill_stage(1, BK);

    for (int kt = 0; kt < NT; kt++) {
        if (kt < NT - 1) cp_wait<1>(); else cp_wait<0>();
        __syncthreads();

        if (kt + 2 < NT) fill_stage((kt + 2) % NSTAGE, (kt + 2) * BK);

        const uint32_t stg = sb + (kt % NSTAGE) * STAGE_B;
        const uint32_t sAh = stg;
        const uint32_t sAl = stg + TILE_B;
        const uint32_t sBh = stg + 2 * TILE_B;
        const uint32_t sBl = stg + 3 * TILE_B;

#pragma unroll
        for (int s = 0; s < 2; s++) {   // two k16 sub-steps per BK=32
            uint32_t a_hi[4][4], a_lo[4][4], b_hi[4][2], b_lo[4][2];
#pragma unroll
            for (int mf = 0; mf < 4; mf++) {
                const uint32_t off =
                    (uint32_t)(((aRowL + mf * 16) * LDS + s * 16 + aColL) * 2);
                ldsm_x4(a_hi[mf][0], a_hi[mf][1], a_hi[mf][2], a_hi[mf][3], sAh + off);
                ldsm_x4(a_lo[mf][0], a_lo[mf][1], a_lo[mf][2], a_lo[mf][3], sAl + off);
            }
#pragma unroll
            for (int p = 0; p < 2; p++) {
                const uint32_t off =
                    (uint32_t)(((bRowL + p * 16) * LDS + s * 16 + bColL) * 2);
                ldsm_x4(b_hi[2 * p][0], b_hi[2 * p][1], b_hi[2 * p + 1][0], b_hi[2 * p + 1][1], sBh + off);
                ldsm_x4(b_lo[2 * p][0], b_lo[2 * p][1], b_lo[2 * p + 1][0], b_lo[2 * p + 1][1], sBl + off);
            }
#pragma unroll
            for (int m = 0; m < 4; m++)
#pragma unroll
                for (int n = 0; n < 4; n++) {
                    mma_bf16(acc[m][n], a_hi[m], b_hi[n]);
                    mma_bf16(acc[m][n], a_hi[m], b_lo[n]);
                    mma_bf16(acc[m][n], a_lo[m], b_hi[n]);
                }
        }
        __syncthreads();
    }

    // ---------------- epilogue ----------------
    const int er = rowBase + warpM + (lane >> 2);
    const int ec = colBase + warpN + (lane & 3) * 2;

    if (MODE == 2) {
        const int b = rowBase >> 11;  // whole 128-row tile in one batch
        float nd[4][2];
#pragma unroll
        for (int n = 0; n < 4; n++) {
            int c = ec + n * 8;
            nd[n][0] = g_num[b * DD + c]     / g_den[b * DD + c];
            nd[n][1] = g_num[b * DD + c + 1] / g_den[b * DD + c + 1];
        }
#pragma unroll
        for (int m = 0; m < 4; m++)
#pragma unroll
            for (int n = 0; n < 4; n++) {
                int c = ec + n * 8;
#pragma unroll
                for (int half = 0; half < 2; half++) {
                    int r = er + m * 16 + half * 8;
                    float y0 = nd[n][0] / (1.0f + __expf(-acc[m][n][half * 2]));
                    float y1 = nd[n][1] / (1.0f + __expf(-acc[m][n][half * 2 + 1]));
                    bf16 h0 = __float2bfloat16(y0);
                    bf16 h1 = __float2bfloat16(y1);
                    bf16 l0 = __float2bfloat16(y0 - __bfloat162float(h0));
                    bf16 l1 = __float2bfloat16(y1 - __bfloat162float(h1));
                    *(__nv_bfloat162*)(g_Ythi + (size_t)r * DD + c) = __nv_bfloat162(h0, h1);
                    *(__nv_bfloat162*)(g_Ytlo + (size_t)r * DD + c) = __nv_bfloat162(l0, l1);
                }
            }
    } else {
        float* C = (MODE == 0) ? g_Kp : (MODE == 1) ? g_Vp : Cout;
#pragma unroll
        for (int m = 0; m < 4; m++)
#pragma unroll
            for (int n = 0; n < 4; n++) {
                int c = ec + n * 8;
#pragma unroll
                for (int half = 0; half < 2; half++) {
                    int r = er + m * 16 + half * 8;
                    *(float2*)(C + (size_t)r * DD + c) =
                        make_float2(acc[m][n][half * 2], acc[m][n][half * 2 + 1]);
                }
            }
    }
}

// ---------------- num/den reduction ----------------
// grid = (DD/128, TT/16) = (8, 128); block = 128 threads
__global__ __launch_bounds__(128) void reduce_kernel() {
    const int d  = blockIdx.x * 128 + threadIdx.x;
    const int t0 = blockIdx.y * 16;

    float num0 = 0.f, num1 = 0.f, num2 = 0.f, num3 = 0.f;
    float den0 = 0.f, den1 = 0.f, den2 = 0.f, den3 = 0.f;

#pragma unroll 4
    for (int t = t0; t < t0 + 16; t++) {
        const size_t off = (size_t)t * DD + d;
        float k0 = g_Kp[off + (size_t)0 * TT * DD];
        float k1 = g_Kp[off + (size_t)1 * TT * DD];
        float k2 = g_Kp[off + (size_t)2 * TT * DD];
        float k3 = g_Kp[off + (size_t)3 * TT * DD];
        float m = fmaxf(fmaxf(k0, k1), fmaxf(k2, k3));
        float e0 = __expf(k0 - m);
        float e1 = __expf(k1 - m);
        float e2 = __expf(k2 - m);
        float e3 = __expf(k3 - m);
        float v0 = g_Vp[off + (size_t)0 * TT * DD];
        float v1 = g_Vp[off + (size_t)1 * TT * DD];
        float v2 = g_Vp[off + (size_t)2 * TT * DD];
        float v3 = g_Vp[off + (size_t)3 * TT * DD];
        num0 = fmaf(e0, v0, num0);  den0 += e0;
        num1 = fmaf(e1, v1, num1);  den1 += e1;
        num2 = fmaf(e2, v2, num2);  den2 += e2;
        num3 = fmaf(e3, v3, num3);  den3 += e3;
    }

    atomicAdd(&g_num[0 * DD + d], num0);
    atomicAdd(&g_num[1 * DD + d], num1);
    atomicAdd(&g_num[2 * DD + d], num2);
    atomicAdd(&g_num[3 * DD + d], num3);
    atomicAdd(&g_den[0 * DD + d], den0);
    atomicAdd(&g_den[1 * DD + d], den1);
    atomicAdd(&g_den[2 * DD + d], den2);
    atomicAdd(&g_den[3 * DD + d], den3);
}

// ---------------------------------------------------------------------------
extern "C" void kernel_launch(void* const* d_in, const int* in_sizes, int n_in,
                              void* d_out, int out_size) {
    const float* q  = (const float*)d_in[0];
    const float* k  = (const float*)d_in[1];
    const float* v  = (const float*)d_in[2];
    const float* Wq = (const float*)d_in[3];
    const float* Wk = (const float*)d_in[4];
    const float* Wv = (const float*)d_in[5];
    const float* Wo = (const float*)d_in[6];
    // d_in[7] = W_bias: provably unused (exp(pos_bias - pos_bias) == 1)
    float* out = (float*)d_out;

    bf16 *qhi, *qlo, *khi, *klo, *vhi, *vlo;
    bf16 *wqh, *wql, *wkh, *wkl, *wvh, *wvl, *woh, *wol;
    cudaGetSymbolAddress((void**)&qhi, g_qhi);  cudaGetSymbolAddress((void**)&qlo, g_qlo);
    cudaGetSymbolAddress((void**)&khi, g_khi);  cudaGetSymbolAddress((void**)&klo, g_klo);
    cudaGetSymbolAddress((void**)&vhi, g_vhi);  cudaGetSymbolAddress((void**)&vlo, g_vlo);
    cudaGetSymbolAddress((void**)&wqh, g_Wqhi); cudaGetSymbolAddress((void**)&wql, g_Wqlo);
    cudaGetSymbolAddress((void**)&wkh, g_Wkhi); cudaGetSymbolAddress((void**)&wkl, g_Wklo);
    cudaGetSymbolAddress((void**)&wvh, g_Wvhi); cudaGetSymbolAddress((void**)&wvl, g_Wvlo);
    cudaGetSymbolAddress((void**)&woh, g_Wohi); cudaGetSymbolAddress((void**)&wol, g_Wolo);

    cudaFuncSetAttribute(mma_gemm<0>, cudaFuncAttributeMaxDynamicSharedMemorySize, SMEM_TOTAL);
    cudaFuncSetAttribute(mma_gemm<1>, cudaFuncAttributeMaxDynamicSharedMemorySize, SMEM_TOTAL);
    cudaFuncSetAttribute(mma_gemm<2>, cudaFuncAttributeMaxDynamicSharedMemorySize, SMEM_TOTAL);
    cudaFuncSetAttribute(mma_gemm<3>, cudaFuncAttributeMaxDynamicSharedMemorySize, SMEM_TOTAL);

    const int nBig = MTOT * KD / 4;
    const int nW   = DD * KD / 4;
    convert_split<<<(nBig + 255) / 256, 256>>>(q, qhi, qlo, nBig);
    convert_split<<<(nBig + 255) / 256, 256>>>(k, khi, klo, nBig);
    convert_split<<<(nBig + 255) / 256, 256>>>(v, vhi, vlo, nBig);
    convert_split<<<(nW + 255) / 256, 256>>>(Wq, wqh, wql, nW);
    convert_split<<<(nW + 255) / 256, 256>>>(Wk, wkh, wkl, nW);
    convert_split<<<(nW + 255) / 256, 256>>>(Wv, wvh, wvl, nW);
    convert_split<<<(nW + 255) / 256, 256>>>(Wo, woh, wol, nW);

    dim3 grid(DD / 128, MTOT / 128);  // (8, 64)

    mma_gemm<0><<<grid, 256, SMEM_TOTAL>>>(khi, klo, wkh, wkl, nullptr);
    mma_gemm<1><<<grid, 256, SMEM_TOTAL>>>(vhi, vlo, wvh, wvl, nullptr);

    init_numden<<<(BB * DD + 255) / 256, 256>>>();
    dim3 redGrid(DD / 128, TT / 16);
    reduce_kernel<<<redGrid, 128>>>();

    mma_gemm<2><<<grid, 256, SMEM_TOTAL>>>(qhi, qlo, wqh, wql, nullptr);
    mma_gemm<3><<<grid, 256, SMEM_TOTAL>>>(nullptr, nullptr, woh, wol, out);
}

// round 5
// speedup vs baseline: 3.2944x; 1.3733x over previous
#include <cuda_runtime.h>
#include <cuda_fp16.h>
#include <cstdint>

// AFT-Full simplified: exp_pos_bias == 1  =>  num/den are per-(b,d) sums over t.
// out = ( sigmoid(q@WqT) * num/den ) @ WoT
//   num[b,d] = sum_t exp(Kp[b,t,d]-m[t,d])*Vp[b,t,d],  den = sum_t exp(Kp-m),
//   m[t,d] = max_b Kp[b,t,d]
// GEMMs: legacy mma.sync fp16 (tcgen05 PTX rejected at compute_103 target).
// Accuracy: fp16 2-term split on A side only (ah*bh + al*bh), err ~2^-11.

#define BB 4
#define TT 2048
#define DD 1024
#define MTOT (BB * TT)   // 8192
#define KD 1024

// ---------------- scratch (static device globals) ----------------
__device__ __half g_qhi[MTOT * KD], g_qlo[MTOT * KD];
__device__ __half g_khi[MTOT * KD], g_klo[MTOT * KD];
__device__ __half g_vhi[MTOT * KD], g_vlo[MTOT * KD];
__device__ __half g_Wqh[DD * KD], g_Wkh[DD * KD], g_Wvh[DD * KD], g_Woh[DD * KD];
__device__ __half g_Ythi[MTOT * DD], g_Ytlo[MTOT * DD];
__device__ float g_Qp[MTOT * DD];
__device__ float g_Kp[MTOT * DD];
__device__ float g_Vp[MTOT * DD];
__device__ float g_num[BB * DD];
__device__ float g_den[BB * DD];

// ---------------- fp32 -> fp16 hi/lo split (activations) ----------------
// 8 floats per thread; hi and lo streamed as uint4.
__global__ __launch_bounds__(256) void act_split(
    const float* __restrict__ src, __half* __restrict__ hi, __half* __restrict__ lo, int n8)
{
    int i = blockIdx.x * blockDim.x + threadIdx.x;
    if (i >= n8) return;
    const float4* s4 = (const float4*)src;
    float4 x0 = s4[2 * i], x1 = s4[2 * i + 1];
    float xs[8] = {x0.x, x0.y, x0.z, x0.w, x1.x, x1.y, x1.z, x1.w};
    __half h[8], l[8];
#pragma unroll
    for (int j = 0; j < 8; j++) {
        h[j] = __float2half(xs[j]);
        l[j] = __float2half(xs[j] - __half2float(h[j]));
    }
    *(uint4*)(hi + (size_t)i * 8) = *(uint4*)h;
    *(uint4*)(lo + (size_t)i * 8) = *(uint4*)l;
}

// fp32 -> fp16 hi only (weights, B side of the split)
__global__ __launch_bounds__(256) void weight_hi(
    const float* __restrict__ src, __half* __restrict__ hi, int n8)
{
    int i = blockIdx.x * blockDim.x + threadIdx.x;
    if (i >= n8) return;
    const float4* s4 = (const float4*)src;
    float4 x0 = s4[2 * i], x1 = s4[2 * i + 1];
    float xs[8] = {x0.x, x0.y, x0.z, x0.w, x1.x, x1.y, x1.z, x1.w};
    __half h[8];
#pragma unroll
    for (int j = 0; j < 8; j++) h[j] = __float2half(xs[j]);
    *(uint4*)(hi + (size_t)i * 8) = *(uint4*)h;
}

__global__ void init_numden() {
    int i = blockIdx.x * blockDim.x + threadIdx.x;
    if (i < BB * DD) { g_num[i] = 0.0f; g_den[i] = 0.0f; }
}

// ---------------- PTX helpers ----------------
__device__ __forceinline__ void ldsm_x4(uint32_t& r0, uint32_t& r1, uint32_t& r2, uint32_t& r3, uint32_t addr) {
    asm volatile("ldmatrix.sync.aligned.m8n8.x4.shared.b16 {%0,%1,%2,%3}, [%4];"
                 : "=r"(r0), "=r"(r1), "=r"(r2), "=r"(r3) : "r"(addr));
}
__device__ __forceinline__ void mma_f16(float* d, const uint32_t* a, const uint32_t* b) {
    asm volatile("mma.sync.aligned.m16n8k16.row.col.f32.f16.f16.f32 "
                 "{%0,%1,%2,%3}, {%4,%5,%6,%7}, {%8,%9}, {%0,%1,%2,%3};"
                 : "+f"(d[0]), "+f"(d[1]), "+f"(d[2]), "+f"(d[3])
                 : "r"(a[0]), "r"(a[1]), "r"(a[2]), "r"(a[3]), "r"(b[0]), "r"(b[1]));
}
__device__ __forceinline__ void cp16(uint32_t s, const void* g) {
    asm volatile("cp.async.cg.shared.global [%0], [%1], 16;" :: "r"(s), "l"(g));
}
__device__ __forceinline__ void cp_commit() {
    asm volatile("cp.async.commit_group;" ::: "memory");
}
template <int N>
__device__ __forceinline__ void cp_wait() {
    asm volatile("cp.async.wait_group %0;" :: "n"(N) : "memory");
}

// ---------------- tensor-core GEMM: C[M,N] = A[M,K] @ B[N,K]^T ----------------
// BM=BN=128, BK=32, 3-stage cp.async pipeline, 256 threads (8 warps 2x4).
// 2 MMAs per k16: a_hi*b + a_lo*b (fp16 split, A side only).
// MODE 0: QKV merged (blockIdx.z selects k/v/q -> Kp/Vp/Qp fp32)
// MODE 1: out = Yt(hi/lo) @ Wo_hi^T -> Cout fp32
constexpr int BK = 32;
constexpr int NT = KD / BK;            // 32 k-tiles
constexpr int LDS = BK + 8;            // 40 halfs = 80 B row stride (conflict-free)
constexpr int TILE_B = 128 * LDS * 2;  // 10240 B per array
constexpr int STAGE_B = 3 * TILE_B;    // 30720 B (Ahi, Alo, Bhi)
constexpr int NSTAGE = 3;
constexpr int SMEM_TOTAL = NSTAGE * STAGE_B;  // 92160 B

template <int MODE>
__global__ __launch_bounds__(256, 1) void hgemm(float* __restrict__ Cout)
{
    extern __shared__ char smem[];
    const uint32_t sb = (uint32_t)__cvta_generic_to_shared(smem);

    const __half *Ahi, *Alo, *Bh;
    float* C;
    if (MODE == 0) {
        if (blockIdx.z == 0)      { Ahi = g_khi; Alo = g_klo; Bh = g_Wkh; C = g_Kp; }
        else if (blockIdx.z == 1) { Ahi = g_vhi; Alo = g_vlo; Bh = g_Wvh; C = g_Vp; }
        else                      { Ahi = g_qhi; Alo = g_qlo; Bh = g_Wqh; C = g_Qp; }
    } else {
        Ahi = g_Ythi; Alo = g_Ytlo; Bh = g_Woh; C = Cout;
    }

    const int tid = threadIdx.x;
    const int wid = tid >> 5, lane = tid & 31;
    const int rowBase = blockIdx.y * 128;
    const int colBase = blockIdx.x * 128;

    const int warpM = (wid >> 2) * 64;
    const int warpN = (wid & 3) * 32;

    const int aRowL = warpM + (lane & 15);
    const int aColL = (lane >> 4) * 8;
    const int bRowL = warpN + ((lane >> 4) << 3) + (lane & 7);
    const int bColL = ((lane >> 3) & 1) * 8;

    float acc[4][4][4];
#pragma unroll
    for (int m = 0; m < 4; m++)
#pragma unroll
        for (int n = 0; n < 4; n++)
#pragma unroll
            for (int r = 0; r < 4; r++) acc[m][n][r] = 0.0f;

    auto fill_stage = [&](int buf, int k0) {
        const uint32_t stg = sb + buf * STAGE_B;
#pragma unroll
        for (int i = 0; i < 2; i++) {
            const int ch = tid + i * 256;
            const int r = ch >> 2, c = ch & 3;
            const uint32_t so = (uint32_t)(r * (LDS * 2) + c * 16);
            const size_t gA = (size_t)(rowBase + r) * KD + k0 + c * 8;
            const size_t gB = (size_t)(colBase + r) * KD + k0 + c * 8;
            cp16(stg + so,              Ahi + gA);
            cp16(stg + TILE_B + so,     Alo + gA);
            cp16(stg + 2 * TILE_B + so, Bh + gB);
        }
        cp_commit();
    };

    fill_stage(0, 0);
    fill_stage(1, BK);

    for (int kt = 0; kt < NT; kt++) {
        if (kt < NT - 1) cp_wait<1>(); else cp_wait<0>();
        __syncthreads();

        if (kt + 2 < NT) fill_stage((kt + 2) % NSTAGE, (kt + 2) * BK);

        const uint32_t stg = sb + (kt % NSTAGE) * STAGE_B;
        const uint32_t sAh = stg;
        const uint32_t sAl = stg + TILE_B;
        const uint32_t sBh = stg + 2 * TILE_B;

#pragma unroll
        for (int s = 0; s < 2; s++) {   // two k16 sub-steps per BK=32
            uint32_t a_hi[4][4], a_lo[4][4], b_h[4][2];
#pragma unroll
            for (int mf = 0; mf < 4; mf++) {
                const uint32_t off =
                    (uint32_t)(((aRowL + mf * 16) * LDS + s * 16 + aColL) * 2);
                ldsm_x4(a_hi[mf][0], a_hi[mf][1], a_hi[mf][2], a_hi[mf][3], sAh + off);
                ldsm_x4(a_lo[mf][0], a_lo[mf][1], a_lo[mf][2], a_lo[mf][3], sAl + off);
            }
#pragma unroll
            for (int p = 0; p < 2; p++) {
                const uint32_t off =
                    (uint32_t)(((bRowL + p * 16) * LDS + s * 16 + bColL) * 2);
                ldsm_x4(b_h[2 * p][0], b_h[2 * p][1], b_h[2 * p + 1][0], b_h[2 * p + 1][1], sBh + off);
            }
#pragma unroll
            for (int m = 0; m < 4; m++)
#pragma unroll
                for (int n = 0; n < 4; n++) {
                    mma_f16(acc[m][n], a_hi[m], b_h[n]);
                    mma_f16(acc[m][n], a_lo[m], b_h[n]);
                }
        }
        __syncthreads();
    }

    // ---------------- epilogue: plain fp32 store ----------------
    const int er = rowBase + warpM + (lane >> 2);
    const int ec = colBase + warpN + (lane & 3) * 2;
#pragma unroll
    for (int m = 0; m < 4; m++)
#pragma unroll
        for (int n = 0; n < 4; n++) {
            int c = ec + n * 8;
#pragma unroll
            for (int half_ = 0; half_ < 2; half_++) {
                int r = er + m * 16 + half_ * 8;
                *(float2*)(C + (size_t)r * DD + c) =
                    make_float2(acc[m][n][half_ * 2], acc[m][n][half_ * 2 + 1]);
            }
        }
}

// ---------------- num/den reduction ----------------
// grid = (DD/128, TT/16) = (8, 128); block = 128 threads
__global__ __launch_bounds__(128) void reduce_kernel() {
    const int d  = blockIdx.x * 128 + threadIdx.x;
    const int t0 = blockIdx.y * 16;

    float num0 = 0.f, num1 = 0.f, num2 = 0.f, num3 = 0.f;
    float den0 = 0.f, den1 = 0.f, den2 = 0.f, den3 = 0.f;

#pragma unroll 4
    for (int t = t0; t < t0 + 16; t++) {
        const size_t off = (size_t)t * DD + d;
        float k0 = g_Kp[off + (size_t)0 * TT * DD];
        float k1 = g_Kp[off + (size_t)1 * TT * DD];
        float k2 = g_Kp[off + (size_t)2 * TT * DD];
        float k3 = g_Kp[off + (size_t)3 * TT * DD];
        float m = fmaxf(fmaxf(k0, k1), fmaxf(k2, k3));
        float e0 = __expf(k0 - m);
        float e1 = __expf(k1 - m);
        float e2 = __expf(k2 - m);
        float e3 = __expf(k3 - m);
        float v0 = g_Vp[off + (size_t)0 * TT * DD];
        float v1 = g_Vp[off + (size_t)1 * TT * DD];
        float v2 = g_Vp[off + (size_t)2 * TT * DD];
        float v3 = g_Vp[off + (size_t)3 * TT * DD];
        num0 = fmaf(e0, v0, num0);  den0 += e0;
        num1 = fmaf(e1, v1, num1);  den1 += e1;
        num2 = fmaf(e2, v2, num2);  den2 += e2;
        num3 = fmaf(e3, v3, num3);  den3 += e3;
    }

    atomicAdd(&g_num[0 * DD + d], num0);
    atomicAdd(&g_num[1 * DD + d], num1);
    atomicAdd(&g_num[2 * DD + d], num2);
    atomicAdd(&g_num[3 * DD + d], num3);
    atomicAdd(&g_den[0 * DD + d], den0);
    atomicAdd(&g_den[1 * DD + d], den1);
    atomicAdd(&g_den[2 * DD + d], den2);
    atomicAdd(&g_den[3 * DD + d], den3);
}

// ---------------- Yt = sigmoid(Qp) * num/den  -> fp16 hi/lo ----------------
// 4 elements per thread; n4 = MTOT*DD/4
__global__ __launch_bounds__(256) void make_yt() {
    int i = blockIdx.x * blockDim.x + threadIdx.x;
    if (i >= MTOT * DD / 4) return;
    const int row = i >> 8;             // DD/4 = 256 float4 per row
    const int c4 = (i & 255) * 4;
    const int b = row >> 11;            // row / 2048

    float4 x = ((const float4*)g_Qp)[i];
    float4 nm = *(const float4*)(g_num + b * DD + c4);
    float4 dn = *(const float4*)(g_den + b * DD + c4);

    float y0 = (nm.x / dn.x) / (1.0f + __expf(-x.x));
    float y1 = (nm.y / dn.y) / (1.0f + __expf(-x.y));
    float y2 = (nm.z / dn.z) / (1.0f + __expf(-x.z));
    float y3 = (nm.w / dn.w) / (1.0f + __expf(-x.w));

    __half h[4], l[4];
    float ys[4] = {y0, y1, y2, y3};
#pragma unroll
    for (int j = 0; j < 4; j++) {
        h[j] = __float2half(ys[j]);
        l[j] = __float2half(ys[j] - __half2float(h[j]));
    }
    *(uint2*)(g_Ythi + (size_t)row * DD + c4) = *(uint2*)h;
    *(uint2*)(g_Ytlo + (size_t)row * DD + c4) = *(uint2*)l;
}

// ---------------------------------------------------------------------------
extern "C" void kernel_launch(void* const* d_in, const int* in_sizes, int n_in,
                              void* d_out, int out_size) {
    const float* q  = (const float*)d_in[0];
    const float* k  = (const float*)d_in[1];
    const float* v  = (const float*)d_in[2];
    const float* Wq = (const float*)d_in[3];
    const float* Wk = (const float*)d_in[4];
    const float* Wv = (const float*)d_in[5];
    const float* Wo = (const float*)d_in[6];
    // d_in[7] = W_bias: provably unused (exp(pos_bias - pos_bias) == 1)
    float* out = (float*)d_out;

    __half *qhi, *qlo, *khi, *klo, *vhi, *vlo, *wqh, *wkh, *wvh, *woh;
    cudaGetSymbolAddress((void**)&qhi, g_qhi);  cudaGetSymbolAddress((void**)&qlo, g_qlo);
    cudaGetSymbolAddress((void**)&khi, g_khi);  cudaGetSymbolAddress((void**)&klo, g_klo);
    cudaGetSymbolAddress((void**)&vhi, g_vhi);  cudaGetSymbolAddress((void**)&vlo, g_vlo);
    cudaGetSymbolAddress((void**)&wqh, g_Wqh);  cudaGetSymbolAddress((void**)&wkh, g_Wkh);
    cudaGetSymbolAddress((void**)&wvh, g_Wvh);  cudaGetSymbolAddress((void**)&woh, g_Woh);

    cudaFuncSetAttribute(hgemm<0>, cudaFuncAttributeMaxDynamicSharedMemorySize, SMEM_TOTAL);
    cudaFuncSetAttribute(hgemm<1>, cudaFuncAttributeMaxDynamicSharedMemorySize, SMEM_TOTAL);

    const int nAct = MTOT * KD / 8;   // 1M
    const int nW   = DD * KD / 8;     // 128K
    act_split<<<nAct / 256, 256>>>(q, qhi, qlo, nAct);
    act_split<<<nAct / 256, 256>>>(k, khi, klo, nAct);
    act_split<<<nAct / 256, 256>>>(v, vhi, vlo, nAct);
    weight_hi<<<nW / 256, 256>>>(Wq, wqh, nW);
    weight_hi<<<nW / 256, 256>>>(Wk, wkh, nW);
    weight_hi<<<nW / 256, 256>>>(Wv, wvh, nW);
    weight_hi<<<nW / 256, 256>>>(Wo, woh, nW);

    // Q, K, V projections in ONE launch (z selects source)
    dim3 qkvGrid(DD / 128, MTOT / 128, 3);  // (8, 64, 3)
    hgemm<0><<<qkvGrid, 256, SMEM_TOTAL>>>(nullptr);

    // num/den over Kp, Vp
    init_numden<<<(BB * DD + 255) / 256, 256>>>();
    dim3 redGrid(DD / 128, TT / 16);
    reduce_kernel<<<redGrid, 128>>>();

    // Yt = sigmoid(Qp) * num/den -> hi/lo
    make_yt<<<(MTOT * DD / 4) / 256, 256>>>();

    // out = Yt @ Wo^T
    dim3 oGrid(DD / 128, MTOT / 128);       // (8, 64)
    hgemm<1><<<oGrid, 256, SMEM_TOTAL>>>(out);
}

// round 6
// speedup vs baseline: 4.3618x; 1.3240x over previous
#include <cuda_runtime.h>
#include <cuda_fp16.h>
#include <cstdint>

// AFT-Full simplified: exp_pos_bias == 1  =>  num/den are per-(b,d) sums over t.
// out = ( sigmoid(q@WqT) * num/den ) @ WoT
// GEMMs: legacy mma.sync fp16 (tcgen05 PTX rejected at compute_103 target).
// Accuracy: fp16 2-term A-side split for K/V/Yt GEMMs; single-term for Q
// (sigmoid compresses the error). 512-thread 128x256 tiles for MMA-latency hiding.

#define BB 4
#define TT 2048
#define DD 1024
#define MTOT (BB * TT)   // 8192
#define KD 1024

// ---------------- scratch (static device globals) ----------------
__device__ __half g_qhi[MTOT * KD];
__device__ __half g_khi[MTOT * KD], g_klo[MTOT * KD];
__device__ __half g_vhi[MTOT * KD], g_vlo[MTOT * KD];
__device__ __half g_Wqh[DD * KD], g_Wkh[DD * KD], g_Wvh[DD * KD], g_Woh[DD * KD];
__device__ __half g_Ythi[MTOT * DD], g_Ytlo[MTOT * DD];
__device__ float g_Qp[MTOT * DD];
__device__ float g_Kp[MTOT * DD];
__device__ float g_Vp[MTOT * DD];
__device__ float g_num[BB * DD];
__device__ float g_den[BB * DD];

// ---------------- fp32 -> fp16 hi/lo split ----------------
__global__ __launch_bounds__(256) void act_split(
    const float* __restrict__ src, __half* __restrict__ hi, __half* __restrict__ lo, int n8)
{
    int i = blockIdx.x * blockDim.x + threadIdx.x;
    if (i >= n8) return;
    const float4* s4 = (const float4*)src;
    float4 x0 = s4[2 * i], x1 = s4[2 * i + 1];
    float xs[8] = {x0.x, x0.y, x0.z, x0.w, x1.x, x1.y, x1.z, x1.w};
    __half h[8], l[8];
#pragma unroll
    for (int j = 0; j < 8; j++) {
        h[j] = __float2half(xs[j]);
        l[j] = __float2half(xs[j] - __half2float(h[j]));
    }
    *(uint4*)(hi + (size_t)i * 8) = *(uint4*)h;
    *(uint4*)(lo + (size_t)i * 8) = *(uint4*)l;
}

// fp32 -> fp16 hi only
__global__ __launch_bounds__(256) void to_half(
    const float* __restrict__ src, __half* __restrict__ hi, int n8)
{
    int i = blockIdx.x * blockDim.x + threadIdx.x;
    if (i >= n8) return;
    const float4* s4 = (const float4*)src;
    float4 x0 = s4[2 * i], x1 = s4[2 * i + 1];
    float xs[8] = {x0.x, x0.y, x0.z, x0.w, x1.x, x1.y, x1.z, x1.w};
    __half h[8];
#pragma unroll
    for (int j = 0; j < 8; j++) h[j] = __float2half(xs[j]);
    *(uint4*)(hi + (size_t)i * 8) = *(uint4*)h;
}

__global__ void init_numden() {
    int i = blockIdx.x * blockDim.x + threadIdx.x;
    if (i < BB * DD) { g_num[i] = 0.0f; g_den[i] = 0.0f; }
}

// ---------------- PTX helpers ----------------
__device__ __forceinline__ void ldsm_x4(uint32_t& r0, uint32_t& r1, uint32_t& r2, uint32_t& r3, uint32_t addr) {
    asm volatile("ldmatrix.sync.aligned.m8n8.x4.shared.b16 {%0,%1,%2,%3}, [%4];"
                 : "=r"(r0), "=r"(r1), "=r"(r2), "=r"(r3) : "r"(addr));
}
__device__ __forceinline__ void mma_f16(float* d, const uint32_t* a, const uint32_t* b) {
    asm volatile("mma.sync.aligned.m16n8k16.row.col.f32.f16.f16.f32 "
                 "{%0,%1,%2,%3}, {%4,%5,%6,%7}, {%8,%9}, {%0,%1,%2,%3};"
                 : "+f"(d[0]), "+f"(d[1]), "+f"(d[2]), "+f"(d[3])
                 : "r"(a[0]), "r"(a[1]), "r"(a[2]), "r"(a[3]), "r"(b[0]), "r"(b[1]));
}
__device__ __forceinline__ void cp16(uint32_t s, const void* g) {
    asm volatile("cp.async.cg.shared.global [%0], [%1], 16;" :: "r"(s), "l"(g));
}
__device__ __forceinline__ void cp_commit() {
    asm volatile("cp.async.commit_group;" ::: "memory");
}
template <int N>
__device__ __forceinline__ void cp_wait() {
    asm volatile("cp.async.wait_group %0;" :: "n"(N) : "memory");
}

// ---------------- tensor-core GEMM: C[M,N] = A[M,K] @ B[N,K]^T ----------------
// BM=128, BN=256, BK=32, 3-stage cp.async pipeline, 512 threads (16 warps, 2x8).
// MODE 0: QKV merged (z: 0=K two-term, 1=V two-term, 2=Q one-term)
// MODE 1: out = Yt(hi/lo) @ Wo_hi^T
constexpr int BK = 32;
constexpr int NT = KD / BK;              // 32 k-tiles
constexpr int LDS = BK + 8;              // 40 halfs = 80 B row stride
constexpr int A_T = 128 * LDS * 2;       // 10240 B per A array
constexpr int B_T = 256 * LDS * 2;       // 20480 B
constexpr int STAGE_B = 2 * A_T + B_T;   // 40960 B (Ahi, Alo, Bhi)
constexpr int NSTAGE = 3;
constexpr int SMEM_TOTAL = NSTAGE * STAGE_B;  // 122880 B

template <int MODE>
__global__ __launch_bounds__(512, 1) void hgemm(float* __restrict__ Cout)
{
    extern __shared__ char smem[];
    const uint32_t sb = (uint32_t)__cvta_generic_to_shared(smem);

    const __half *Ahi, *Alo, *Bh;
    float* C;
    bool two;  // uniform per CTA
    if (MODE == 0) {
        if (blockIdx.z == 0)      { Ahi = g_khi; Alo = g_klo; Bh = g_Wkh; C = g_Kp; two = true; }
        else if (blockIdx.z == 1) { Ahi = g_vhi; Alo = g_vlo; Bh = g_Wvh; C = g_Vp; two = true; }
        else                      { Ahi = g_qhi; Alo = g_qhi; Bh = g_Wqh; C = g_Qp; two = false; }
    } else {
        Ahi = g_Ythi; Alo = g_Ytlo; Bh = g_Woh; C = Cout; two = true;
    }

    const int tid = threadIdx.x;
    const int wid = tid >> 5, lane = tid & 31;
    const int rowBase = blockIdx.y * 128;
    const int colBase = blockIdx.x * 256;

    // 16 warps: 2 (M) x 8 (N); warp tile 64x32
    const int warpM = (wid >> 3) * 64;
    const int warpN = (wid & 7) * 32;

    const int aRowL = warpM + (lane & 15);
    const int aColL = (lane >> 4) * 8;
    const int bRowL = warpN + ((lane >> 4) << 3) + (lane & 7);
    const int bColL = ((lane >> 3) & 1) * 8;

    float acc[4][4][4];
#pragma unroll
    for (int m = 0; m < 4; m++)
#pragma unroll
        for (int n = 0; n < 4; n++)
#pragma unroll
            for (int r = 0; r < 4; r++) acc[m][n][r] = 0.0f;

    auto fill_stage = [&](int buf, int k0) {
        const uint32_t stg = sb + buf * STAGE_B;
        {   // A arrays: 512 16B-chunks each; one per thread
            const int r = tid >> 2, c = tid & 3;
            const uint32_t so = (uint32_t)(r * (LDS * 2) + c * 16);
            const size_t gA = (size_t)(rowBase + r) * KD + k0 + c * 8;
            cp16(stg + so, Ahi + gA);
            if (two) cp16(stg + A_T + so, Alo + gA);
        }
#pragma unroll
        for (int i = 0; i < 2; i++) {  // B: 1024 chunks; two per thread
            const int ch = tid + i * 512;
            const int r = ch >> 2, c = ch & 3;
            const uint32_t so = (uint32_t)(r * (LDS * 2) + c * 16);
            const size_t gB = (size_t)(colBase + r) * KD + k0 + c * 8;
            cp16(stg + 2 * A_T + so, Bh + gB);
        }
        cp_commit();
    };

    fill_stage(0, 0);
    fill_stage(1, BK);

    for (int kt = 0; kt < NT; kt++) {
        if (kt < NT - 1) cp_wait<1>(); else cp_wait<0>();
        __syncthreads();

        if (kt + 2 < NT) fill_stage((kt + 2) % NSTAGE, (kt + 2) * BK);

        const uint32_t stg = sb + (kt % NSTAGE) * STAGE_B;
        const uint32_t sAh = stg;
        const uint32_t sAl = stg + A_T;
        const uint32_t sBh = stg + 2 * A_T;

#pragma unroll
        for (int s = 0; s < 2; s++) {   // two k16 sub-steps per BK=32
            uint32_t a[4][4], b[4][2];
#pragma unroll
            for (int p = 0; p < 2; p++) {
                const uint32_t off =
                    (uint32_t)(((bRowL + p * 16) * LDS + s * 16 + bColL) * 2);
                ldsm_x4(b[2 * p][0], b[2 * p][1], b[2 * p + 1][0], b[2 * p + 1][1], sBh + off);
            }
#pragma unroll
            for (int mf = 0; mf < 4; mf++) {
                const uint32_t off =
                    (uint32_t)(((aRowL + mf * 16) * LDS + s * 16 + aColL) * 2);
                ldsm_x4(a[mf][0], a[mf][1], a[mf][2], a[mf][3], sAh + off);
            }
#pragma unroll
            for (int m = 0; m < 4; m++)
#pragma unroll
                for (int n = 0; n < 4; n++)
                    mma_f16(acc[m][n], a[m], b[n]);
            if (two) {
#pragma unroll
                for (int mf = 0; mf < 4; mf++) {
                    const uint32_t off =
                        (uint32_t)(((aRowL + mf * 16) * LDS + s * 16 + aColL) * 2);
                    ldsm_x4(a[mf][0], a[mf][1], a[mf][2], a[mf][3], sAl + off);
                }
#pragma unroll
                for (int m = 0; m < 4; m++)
#pragma unroll
                    for (int n = 0; n < 4; n++)
                        mma_f16(acc[m][n], a[m], b[n]);
            }
        }
        __syncthreads();
    }

    // ---------------- epilogue: fp32 store ----------------
    const int er = rowBase + warpM + (lane >> 2);
    const int ec = colBase + warpN + (lane & 3) * 2;
#pragma unroll
    for (int m = 0; m < 4; m++)
#pragma unroll
        for (int n = 0; n < 4; n++) {
            int c = ec + n * 8;
#pragma unroll
            for (int half_ = 0; half_ < 2; half_++) {
                int r = er + m * 16 + half_ * 8;
                *(float2*)(C + (size_t)r * DD + c) =
                    make_float2(acc[m][n][half_ * 2], acc[m][n][half_ * 2 + 1]);
            }
        }
}

// ---------------- num/den reduction ----------------
__global__ __launch_bounds__(128) void reduce_kernel() {
    const int d  = blockIdx.x * 128 + threadIdx.x;
    const int t0 = blockIdx.y * 16;

    float num0 = 0.f, num1 = 0.f, num2 = 0.f, num3 = 0.f;
    float den0 = 0.f, den1 = 0.f, den2 = 0.f, den3 = 0.f;

#pragma unroll 4
    for (int t = t0; t < t0 + 16; t++) {
        const size_t off = (size_t)t * DD + d;
        float k0 = g_Kp[off + (size_t)0 * TT * DD];
        float k1 = g_Kp[off + (size_t)1 * TT * DD];
        float k2 = g_Kp[off + (size_t)2 * TT * DD];
        float k3 = g_Kp[off + (size_t)3 * TT * DD];
        float m = fmaxf(fmaxf(k0, k1), fmaxf(k2, k3));
        float e0 = __expf(k0 - m);
        float e1 = __expf(k1 - m);
        float e2 = __expf(k2 - m);
        float e3 = __expf(k3 - m);
        float v0 = g_Vp[off + (size_t)0 * TT * DD];
        float v1 = g_Vp[off + (size_t)1 * TT * DD];
        float v2 = g_Vp[off + (size_t)2 * TT * DD];
        float v3 = g_Vp[off + (size_t)3 * TT * DD];
        num0 = fmaf(e0, v0, num0);  den0 += e0;
        num1 = fmaf(e1, v1, num1);  den1 += e1;
        num2 = fmaf(e2, v2, num2);  den2 += e2;
        num3 = fmaf(e3, v3, num3);  den3 += e3;
    }

    atomicAdd(&g_num[0 * DD + d], num0);
    atomicAdd(&g_num[1 * DD + d], num1);
    atomicAdd(&g_num[2 * DD + d], num2);
    atomicAdd(&g_num[3 * DD + d], num3);
    atomicAdd(&g_den[0 * DD + d], den0);
    atomicAdd(&g_den[1 * DD + d], den1);
    atomicAdd(&g_den[2 * DD + d], den2);
    atomicAdd(&g_den[3 * DD + d], den3);
}

// ---------------- Yt = sigmoid(Qp) * num/den  -> fp16 hi/lo ----------------
__global__ __launch_bounds__(256) void make_yt() {
    int i = blockIdx.x * blockDim.x + threadIdx.x;
    if (i >= MTOT * DD / 4) return;
    const int row = i >> 8;
    const int c4 = (i & 255) * 4;
    const int b = row >> 11;

    float4 x = ((const float4*)g_Qp)[i];
    float4 nm = *(const float4*)(g_num + b * DD + c4);
    float4 dn = *(const float4*)(g_den + b * DD + c4);

    float ys[4];
    ys[0] = (nm.x / dn.x) / (1.0f + __expf(-x.x));
    ys[1] = (nm.y / dn.y) / (1.0f + __expf(-x.y));
    ys[2] = (nm.z / dn.z) / (1.0f + __expf(-x.z));
    ys[3] = (nm.w / dn.w) / (1.0f + __expf(-x.w));

    __half h[4], l[4];
#pragma unroll
    for (int j = 0; j < 4; j++) {
        h[j] = __float2half(ys[j]);
        l[j] = __float2half(ys[j] - __half2float(h[j]));
    }
    *(uint2*)(g_Ythi + (size_t)row * DD + c4) = *(uint2*)h;
    *(uint2*)(g_Ytlo + (size_t)row * DD + c4) = *(uint2*)l;
}

// ---------------------------------------------------------------------------
extern "C" void kernel_launch(void* const* d_in, const int* in_sizes, int n_in,
                              void* d_out, int out_size) {
    const float* q  = (const float*)d_in[0];
    const float* k  = (const float*)d_in[1];
    const float* v  = (const float*)d_in[2];
    const float* Wq = (const float*)d_in[3];
    const float* Wk = (const float*)d_in[4];
    const float* Wv = (const float*)d_in[5];
    const float* Wo = (const float*)d_in[6];
    // d_in[7] = W_bias: provably unused (exp(pos_bias - pos_bias) == 1)
    float* out = (float*)d_out;

    __half *qhi, *khi, *klo, *vhi, *vlo, *wqh, *wkh, *wvh, *woh;
    cudaGetSymbolAddress((void**)&qhi, g_qhi);
    cudaGetSymbolAddress((void**)&khi, g_khi);  cudaGetSymbolAddress((void**)&klo, g_klo);
    cudaGetSymbolAddress((void**)&vhi, g_vhi);  cudaGetSymbolAddress((void**)&vlo, g_vlo);
    cudaGetSymbolAddress((void**)&wqh, g_Wqh);  cudaGetSymbolAddress((void**)&wkh, g_Wkh);
    cudaGetSymbolAddress((void**)&wvh, g_Wvh);  cudaGetSymbolAddress((void**)&woh, g_Woh);

    cudaFuncSetAttribute(hgemm<0>, cudaFuncAttributeMaxDynamicSharedMemorySize, SMEM_TOTAL);
    cudaFuncSetAttribute(hgemm<1>, cudaFuncAttributeMaxDynamicSharedMemorySize, SMEM_TOTAL);

    const int nAct = MTOT * KD / 8;   // 1M
    const int nW   = DD * KD / 8;     // 128K
    to_half<<<nAct / 256, 256>>>(q, qhi, nAct);
    act_split<<<nAct / 256, 256>>>(k, khi, klo, nAct);
    act_split<<<nAct / 256, 256>>>(v, vhi, vlo, nAct);
    to_half<<<nW / 256, 256>>>(Wq, wqh, nW);
    to_half<<<nW / 256, 256>>>(Wk, wkh, nW);
    to_half<<<nW / 256, 256>>>(Wv, wvh, nW);
    to_half<<<nW / 256, 256>>>(Wo, woh, nW);

    // Q, K, V projections in ONE launch (z selects source)
    dim3 qkvGrid(DD / 256, MTOT / 128, 3);  // (4, 64, 3)
    hgemm<0><<<qkvGrid, 512, SMEM_TOTAL>>>(nullptr);

    // num/den over Kp, Vp
    init_numden<<<(BB * DD + 255) / 256, 256>>>();
    dim3 redGrid(DD / 128, TT / 16);
    reduce_kernel<<<redGrid, 128>>>();

    // Yt = sigmoid(Qp) * num/den -> hi/lo
    make_yt<<<(MTOT * DD / 4) / 256, 256>>>();

    // out = Yt @ Wo^T
    dim3 oGrid(DD / 256, MTOT / 128);       // (4, 64)
    hgemm<1><<<oGrid, 512, SMEM_TOTAL>>>(out);
}

// round 7
// speedup vs baseline: 5.5717x; 1.2774x over previous
#include <cuda_runtime.h>
#include <cuda_fp16.h>
#include <cstdint>

// AFT-Full simplified: exp_pos_bias == 1  =>  num/den are per-(b,d) sums over t.
// out = ( sigmoid(q@WqT) * num/den ) @ WoT
// GEMMs: legacy mma.sync fp16, single-term (error dominated by fp16 weight
// quantization either way; measured R5/R6 delta proved lo-terms ~useless).
// 512-thread 128x256 tiles; Q GEMM has fused sigmoid*num/den epilogue.

#define BB 4
#define TT 2048
#define DD 1024
#define MTOT (BB * TT)   // 8192
#define KD 1024

// ---------------- scratch (static device globals) ----------------
__device__ __half g_qh[MTOT * KD];
__device__ __half g_kh[MTOT * KD];
__device__ __half g_vh[MTOT * KD];
__device__ __half g_Wqh[DD * KD], g_Wkh[DD * KD], g_Wvh[DD * KD], g_Woh[DD * KD];
__device__ __half g_Yth[MTOT * DD];
__device__ float g_Kp[MTOT * DD];
__device__ float g_Vp[MTOT * DD];
__device__ float g_num[BB * DD];
__device__ float g_den[BB * DD];

// ---------------- fp32 -> fp16 converts (z-indexed) ----------------
__global__ __launch_bounds__(256) void conv_acts(
    const float* __restrict__ q, const float* __restrict__ k, const float* __restrict__ v)
{
    const float* src = (blockIdx.z == 0) ? q : (blockIdx.z == 1) ? k : v;
    __half* dst = (blockIdx.z == 0) ? g_qh : (blockIdx.z == 1) ? g_kh : g_vh;
    int i = blockIdx.x * blockDim.x + threadIdx.x;   // n8 = MTOT*KD/8
    const float4* s4 = (const float4*)src;
    float4 x0 = s4[2 * i], x1 = s4[2 * i + 1];
    float xs[8] = {x0.x, x0.y, x0.z, x0.w, x1.x, x1.y, x1.z, x1.w};
    __half h[8];
#pragma unroll
    for (int j = 0; j < 8; j++) h[j] = __float2half(xs[j]);
    *(uint4*)(dst + (size_t)i * 8) = *(uint4*)h;
}

__global__ __launch_bounds__(256) void conv_weights(
    const float* __restrict__ wq, const float* __restrict__ wk,
    const float* __restrict__ wv, const float* __restrict__ wo)
{
    const float* src = (blockIdx.z == 0) ? wq : (blockIdx.z == 1) ? wk
                     : (blockIdx.z == 2) ? wv : wo;
    __half* dst = (blockIdx.z == 0) ? g_Wqh : (blockIdx.z == 1) ? g_Wkh
                : (blockIdx.z == 2) ? g_Wvh : g_Woh;
    int i = blockIdx.x * blockDim.x + threadIdx.x;   // n8 = DD*KD/8
    const float4* s4 = (const float4*)src;
    float4 x0 = s4[2 * i], x1 = s4[2 * i + 1];
    float xs[8] = {x0.x, x0.y, x0.z, x0.w, x1.x, x1.y, x1.z, x1.w};
    __half h[8];
#pragma unroll
    for (int j = 0; j < 8; j++) h[j] = __float2half(xs[j]);
    *(uint4*)(dst + (size_t)i * 8) = *(uint4*)h;
}

__global__ void init_numden() {
    int i = blockIdx.x * blockDim.x + threadIdx.x;
    if (i < BB * DD) { g_num[i] = 0.0f; g_den[i] = 0.0f; }
}

// ---------------- PTX helpers ----------------
__device__ __forceinline__ void ldsm_x4(uint32_t& r0, uint32_t& r1, uint32_t& r2, uint32_t& r3, uint32_t addr) {
    asm volatile("ldmatrix.sync.aligned.m8n8.x4.shared.b16 {%0,%1,%2,%3}, [%4];"
                 : "=r"(r0), "=r"(r1), "=r"(r2), "=r"(r3) : "r"(addr));
}
__device__ __forceinline__ void mma_f16(float* d, const uint32_t* a, const uint32_t* b) {
    asm volatile("mma.sync.aligned.m16n8k16.row.col.f32.f16.f16.f32 "
                 "{%0,%1,%2,%3}, {%4,%5,%6,%7}, {%8,%9}, {%0,%1,%2,%3};"
                 : "+f"(d[0]), "+f"(d[1]), "+f"(d[2]), "+f"(d[3])
                 : "r"(a[0]), "r"(a[1]), "r"(a[2]), "r"(a[3]), "r"(b[0]), "r"(b[1]));
}
__device__ __forceinline__ void cp16(uint32_t s, const void* g) {
    asm volatile("cp.async.cg.shared.global [%0], [%1], 16;" :: "r"(s), "l"(g));
}
__device__ __forceinline__ void cp_commit() {
    asm volatile("cp.async.commit_group;" ::: "memory");
}
template <int N>
__device__ __forceinline__ void cp_wait() {
    asm volatile("cp.async.wait_group %0;" :: "n"(N) : "memory");
}

// ---------------- tensor-core GEMM: C[M,N] = A[M,K] @ B[N,K]^T ----------------
// BM=128, BN=256, BK=32, 3-stage cp.async pipeline, 512 threads (16 warps 2x8).
// MODE 0: K/V merged (z: 0=K->Kp, 1=V->Vp), fp32 store
// MODE 1: Q with fused epilogue: Yt = sigmoid(acc)*num/den -> g_Yth (fp16)
// MODE 2: out = Yt @ Wo^T -> Cout fp32
constexpr int BK = 32;
constexpr int NT = KD / BK;              // 32 k-tiles
constexpr int LDS = BK + 8;              // 40 halfs = 80 B row stride
constexpr int A_T = 128 * LDS * 2;       // 10240 B
constexpr int B_T = 256 * LDS * 2;       // 20480 B
constexpr int STAGE_B = A_T + B_T;       // 30720 B
constexpr int NSTAGE = 3;
constexpr int SMEM_TOTAL = NSTAGE * STAGE_B;  // 92160 B

template <int MODE>
__global__ __launch_bounds__(512, 1) void hgemm(float* __restrict__ Cout)
{
    extern __shared__ char smem[];
    const uint32_t sb = (uint32_t)__cvta_generic_to_shared(smem);

    const __half *A, *Bh;
    float* C = nullptr;
    if (MODE == 0) {
        if (blockIdx.z == 0) { A = g_kh; Bh = g_Wkh; C = g_Kp; }
        else                 { A = g_vh; Bh = g_Wvh; C = g_Vp; }
    } else if (MODE == 1) {
        A = g_qh; Bh = g_Wqh;
    } else {
        A = g_Yth; Bh = g_Woh; C = Cout;
    }

    const int tid = threadIdx.x;
    const int wid = tid >> 5, lane = tid & 31;
    const int rowBase = blockIdx.y * 128;
    const int colBase = blockIdx.x * 256;

    // 16 warps: 2 (M) x 8 (N); warp tile 64x32
    const int warpM = (wid >> 3) * 64;
    const int warpN = (wid & 7) * 32;

    const int aRowL = warpM + (lane & 15);
    const int aColL = (lane >> 4) * 8;
    const int bRowL = warpN + ((lane >> 4) << 3) + (lane & 7);
    const int bColL = ((lane >> 3) & 1) * 8;

    float acc[4][4][4];
#pragma unroll
    for (int m = 0; m < 4; m++)
#pragma unroll
        for (int n = 0; n < 4; n++)
#pragma unroll
            for (int r = 0; r < 4; r++) acc[m][n][r] = 0.0f;

    auto fill_stage = [&](int buf, int k0) {
        const uint32_t stg = sb + buf * STAGE_B;
        {   // A: 512 16B-chunks, one per thread
            const int r = tid >> 2, c = tid & 3;
            const uint32_t so = (uint32_t)(r * (LDS * 2) + c * 16);
            cp16(stg + so, A + (size_t)(rowBase + r) * KD + k0 + c * 8);
        }
#pragma unroll
        for (int i = 0; i < 2; i++) {  // B: 1024 chunks, two per thread
            const int ch = tid + i * 512;
            const int r = ch >> 2, c = ch & 3;
            const uint32_t so = (uint32_t)(r * (LDS * 2) + c * 16);
            cp16(stg + A_T + so, Bh + (size_t)(colBase + r) * KD + k0 + c * 8);
        }
        cp_commit();
    };

    fill_stage(0, 0);
    fill_stage(1, BK);

    for (int kt = 0; kt < NT; kt++) {
        if (kt < NT - 1) cp_wait<1>(); else cp_wait<0>();
        __syncthreads();

        if (kt + 2 < NT) fill_stage((kt + 2) % NSTAGE, (kt + 2) * BK);

        const uint32_t stg = sb + (kt % NSTAGE) * STAGE_B;
        const uint32_t sA = stg;
        const uint32_t sB = stg + A_T;

#pragma unroll
        for (int s = 0; s < 2; s++) {   // two k16 sub-steps per BK=32
            uint32_t a[4][4], b[4][2];
#pragma unroll
            for (int p = 0; p < 2; p++) {
                const uint32_t off =
                    (uint32_t)(((bRowL + p * 16) * LDS + s * 16 + bColL) * 2);
                ldsm_x4(b[2 * p][0], b[2 * p][1], b[2 * p + 1][0], b[2 * p + 1][1], sB + off);
            }
#pragma unroll
            for (int mf = 0; mf < 4; mf++) {
                const uint32_t off =
                    (uint32_t)(((aRowL + mf * 16) * LDS + s * 16 + aColL) * 2);
                ldsm_x4(a[mf][0], a[mf][1], a[mf][2], a[mf][3], sA + off);
            }
#pragma unroll
            for (int m = 0; m < 4; m++)
#pragma unroll
                for (int n = 0; n < 4; n++)
                    mma_f16(acc[m][n], a[m], b[n]);
        }
        __syncthreads();
    }

    // ---------------- epilogue ----------------
    const int er = rowBase + warpM + (lane >> 2);
    const int ec = colBase + warpN + (lane & 3) * 2;

    if (MODE == 1) {
        // ratio = num/den for this tile's 256 columns (batch uniform per CTA)
        float* snd = (float*)smem;
        const int b = rowBase >> 11;
        if (tid < 256)
            snd[tid] = g_num[b * DD + colBase + tid] / g_den[b * DD + colBase + tid];
        __syncthreads();
#pragma unroll
        for (int m = 0; m < 4; m++)
#pragma unroll
            for (int n = 0; n < 4; n++) {
                const int cl = (ec - colBase) + n * 8;
                const float r0 = snd[cl], r1 = snd[cl + 1];
#pragma unroll
                for (int h = 0; h < 2; h++) {
                    const int r = er + m * 16 + h * 8;
                    float y0 = r0 / (1.0f + __expf(-acc[m][n][h * 2]));
                    float y1 = r1 / (1.0f + __expf(-acc[m][n][h * 2 + 1]));
                    *(__half2*)(g_Yth + (size_t)r * DD + colBase + cl) =
                        __floats2half2_rn(y0, y1);
                }
            }
    } else {
#pragma unroll
        for (int m = 0; m < 4; m++)
#pragma unroll
            for (int n = 0; n < 4; n++) {
                const int c = ec + n * 8;
#pragma unroll
                for (int h = 0; h < 2; h++) {
                    const int r = er + m * 16 + h * 8;
                    *(float2*)(C + (size_t)r * DD + c) =
                        make_float2(acc[m][n][h * 2], acc[m][n][h * 2 + 1]);
                }
            }
    }
}

// ---------------- num/den reduction ----------------
__global__ __launch_bounds__(128) void reduce_kernel() {
    const int d  = blockIdx.x * 128 + threadIdx.x;
    const int t0 = blockIdx.y * 16;

    float num0 = 0.f, num1 = 0.f, num2 = 0.f, num3 = 0.f;
    float den0 = 0.f, den1 = 0.f, den2 = 0.f, den3 = 0.f;

#pragma unroll 4
    for (int t = t0; t < t0 + 16; t++) {
        const size_t off = (size_t)t * DD + d;
        float k0 = g_Kp[off + (size_t)0 * TT * DD];
        float k1 = g_Kp[off + (size_t)1 * TT * DD];
        float k2 = g_Kp[off + (size_t)2 * TT * DD];
        float k3 = g_Kp[off + (size_t)3 * TT * DD];
        float m = fmaxf(fmaxf(k0, k1), fmaxf(k2, k3));
        float e0 = __expf(k0 - m);
        float e1 = __expf(k1 - m);
        float e2 = __expf(k2 - m);
        float e3 = __expf(k3 - m);
        float v0 = g_Vp[off + (size_t)0 * TT * DD];
        float v1 = g_Vp[off + (size_t)1 * TT * DD];
        float v2 = g_Vp[off + (size_t)2 * TT * DD];
        float v3 = g_Vp[off + (size_t)3 * TT * DD];
        num0 = fmaf(e0, v0, num0);  den0 += e0;
        num1 = fmaf(e1, v1, num1);  den1 += e1;
        num2 = fmaf(e2, v2, num2);  den2 += e2;
        num3 = fmaf(e3, v3, num3);  den3 += e3;
    }

    atomicAdd(&g_num[0 * DD + d], num0);
    atomicAdd(&g_num[1 * DD + d], num1);
    atomicAdd(&g_num[2 * DD + d], num2);
    atomicAdd(&g_num[3 * DD + d], num3);
    atomicAdd(&g_den[0 * DD + d], den0);
    atomicAdd(&g_den[1 * DD + d], den1);
    atomicAdd(&g_den[2 * DD + d], den2);
    atomicAdd(&g_den[3 * DD + d], den3);
}

// ---------------------------------------------------------------------------
extern "C" void kernel_launch(void* const* d_in, const int* in_sizes, int n_in,
                              void* d_out, int out_size) {
    const float* q  = (const float*)d_in[0];
    const float* k  = (const float*)d_in[1];
    const float* v  = (const float*)d_in[2];
    const float* Wq = (const float*)d_in[3];
    const float* Wk = (const float*)d_in[4];
    const float* Wv = (const float*)d_in[5];
    const float* Wo = (const float*)d_in[6];
    // d_in[7] = W_bias: provably unused (exp(pos_bias - pos_bias) == 1)
    float* out = (float*)d_out;

    cudaFuncSetAttribute(hgemm<0>, cudaFuncAttributeMaxDynamicSharedMemorySize, SMEM_TOTAL);
    cudaFuncSetAttribute(hgemm<1>, cudaFuncAttributeMaxDynamicSharedMemorySize, SMEM_TOTAL);
    cudaFuncSetAttribute(hgemm<2>, cudaFuncAttributeMaxDynamicSharedMemorySize, SMEM_TOTAL);

    const int nAct = MTOT * KD / 8;   // 1M elements of 8 floats
    const int nW   = DD * KD / 8;     // 128K
    dim3 aGrid(nAct / 256, 1, 3);
    conv_acts<<<aGrid, 256>>>(q, k, v);
    dim3 wGrid(nW / 256, 1, 4);
    conv_weights<<<wGrid, 256>>>(Wq, Wk, Wv, Wo);

    // K, V projections (merged launch)
    dim3 kvGrid(DD / 256, MTOT / 128, 2);   // (4, 64, 2)
    hgemm<0><<<kvGrid, 512, SMEM_TOTAL>>>(nullptr);

    // num/den over Kp, Vp
    init_numden<<<(BB * DD + 255) / 256, 256>>>();
    dim3 redGrid(DD / 128, TT / 16);        // (8, 128)
    reduce_kernel<<<redGrid, 128>>>();

    // Q projection + fused sigmoid*num/den epilogue -> Yt (fp16)
    dim3 qGrid(DD / 256, MTOT / 128);       // (4, 64)
    hgemm<1><<<qGrid, 512, SMEM_TOTAL>>>(nullptr);

    // out = Yt @ Wo^T
    hgemm<2><<<qGrid, 512, SMEM_TOTAL>>>(out);
}

// round 8
// speedup vs baseline: 5.7035x; 1.0237x over previous
#include <cuda_runtime.h>
#include <cuda_fp16.h>
#include <cstdint>

// AFT-Full simplified: exp_pos_bias == 1  =>  num/den are per-(b,d) sums over t.
// out = ( sigmoid(q@WqT) * num/den ) @ WoT
// GEMMs: legacy mma.sync fp16, single-term. 512-thread 128x256 tiles.
// This round: single merged convert kernel (MLP-4 streaming), fp16 Kp/Vp,
// init folded into convert.

#define BB 4
#define TT 2048
#define DD 1024
#define MTOT (BB * TT)   // 8192
#define KD 1024

// ---------------- scratch (static device globals) ----------------
__device__ __half g_qh[MTOT * KD];
__device__ __half g_kh[MTOT * KD];
__device__ __half g_vh[MTOT * KD];
__device__ __half g_Wqh[DD * KD], g_Wkh[DD * KD], g_Wvh[DD * KD], g_Woh[DD * KD];
__device__ __half g_Yth[MTOT * DD];
__device__ __half g_Kph[MTOT * DD];
__device__ __half g_Vph[MTOT * DD];
__device__ float g_num[BB * DD];
__device__ float g_den[BB * DD];

// ---------------- merged fp32 -> fp16 convert, all 7 tensors ----------------
// Chunk = 16 floats. acts: 524288 chunks each; weights: 65536 each.
// Total chunks = 3*524288 + 4*65536 = 1835008 = 7168 blocks * 256 threads.
constexpr int ACT_CH = MTOT * KD / 16;   // 524288
constexpr int W_CH   = DD * KD / 16;     // 65536
constexpr int TOT_CH = 3 * ACT_CH + 4 * W_CH;

__global__ __launch_bounds__(256) void convert_all(
    const float* __restrict__ q, const float* __restrict__ k, const float* __restrict__ v,
    const float* __restrict__ wq, const float* __restrict__ wk,
    const float* __restrict__ wv, const float* __restrict__ wo)
{
    const int i = blockIdx.x * blockDim.x + threadIdx.x;

    // fold num/den zeroing into this kernel (first 4096 threads)
    if (i < BB * DD) { g_num[i] = 0.0f; g_den[i] = 0.0f; }

    const float* src;
    __half* dst;
    size_t off;  // chunk offset within tensor
    if (i < ACT_CH)              { src = q;  dst = g_qh;  off = i; }
    else if (i < 2 * ACT_CH)     { src = k;  dst = g_kh;  off = i - ACT_CH; }
    else if (i < 3 * ACT_CH)     { src = v;  dst = g_vh;  off = i - 2 * ACT_CH; }
    else {
        int w = i - 3 * ACT_CH;
        int t = w >> 16;         // 65536 chunks per weight tensor
        off = w & 65535;
        if (t == 0)      { src = wq; dst = g_Wqh; }
        else if (t == 1) { src = wk; dst = g_Wkh; }
        else if (t == 2) { src = wv; dst = g_Wvh; }
        else             { src = wo; dst = g_Woh; }
    }

    const float4* s4 = (const float4*)(src) + off * 4;
    float4 x0 = s4[0], x1 = s4[1], x2 = s4[2], x3 = s4[3];  // 4 loads in flight
    float xs[16] = {x0.x, x0.y, x0.z, x0.w, x1.x, x1.y, x1.z, x1.w,
                    x2.x, x2.y, x2.z, x2.w, x3.x, x3.y, x3.z, x3.w};
    __half h[16];
#pragma unroll
    for (int j = 0; j < 16; j++) h[j] = __float2half(xs[j]);
    uint4* d4 = (uint4*)(dst + off * 16);
    d4[0] = *(uint4*)(h);
    d4[1] = *(uint4*)(h + 8);
}

// ---------------- PTX helpers ----------------
__device__ __forceinline__ void ldsm_x4(uint32_t& r0, uint32_t& r1, uint32_t& r2, uint32_t& r3, uint32_t addr) {
    asm volatile("ldmatrix.sync.aligned.m8n8.x4.shared.b16 {%0,%1,%2,%3}, [%4];"
                 : "=r"(r0), "=r"(r1), "=r"(r2), "=r"(r3) : "r"(addr));
}
__device__ __forceinline__ void mma_f16(float* d, const uint32_t* a, const uint32_t* b) {
    asm volatile("mma.sync.aligned.m16n8k16.row.col.f32.f16.f16.f32 "
                 "{%0,%1,%2,%3}, {%4,%5,%6,%7}, {%8,%9}, {%0,%1,%2,%3};"
                 : "+f"(d[0]), "+f"(d[1]), "+f"(d[2]), "+f"(d[3])
                 : "r"(a[0]), "r"(a[1]), "r"(a[2]), "r"(a[3]), "r"(b[0]), "r"(b[1]));
}
__device__ __forceinline__ void cp16(uint32_t s, const void* g) {
    asm volatile("cp.async.cg.shared.global [%0], [%1], 16;" :: "r"(s), "l"(g));
}
__device__ __forceinline__ void cp_commit() {
    asm volatile("cp.async.commit_group;" ::: "memory");
}
template <int N>
__device__ __forceinline__ void cp_wait() {
    asm volatile("cp.async.wait_group %0;" :: "n"(N) : "memory");
}

// ---------------- tensor-core GEMM: C[M,N] = A[M,K] @ B[N,K]^T ----------------
// BM=128, BN=256, BK=32, 3-stage cp.async pipeline, 512 threads (16 warps 2x8).
// MODE 0: K/V merged (z: 0=K->Kph, 1=V->Vph), fp16 store
// MODE 1: Q with fused epilogue: Yt = sigmoid(acc)*num/den -> g_Yth (fp16)
// MODE 2: out = Yt @ Wo^T -> Cout fp32
constexpr int BK = 32;
constexpr int NT = KD / BK;              // 32 k-tiles
constexpr int LDS = BK + 8;              // 40 halfs = 80 B row stride
constexpr int A_T = 128 * LDS * 2;       // 10240 B
constexpr int B_T = 256 * LDS * 2;       // 20480 B
constexpr int STAGE_B = A_T + B_T;       // 30720 B
constexpr int NSTAGE = 3;
constexpr int SMEM_TOTAL = NSTAGE * STAGE_B;  // 92160 B

template <int MODE>
__global__ __launch_bounds__(512, 1) void hgemm(float* __restrict__ Cout)
{
    extern __shared__ char smem[];
    const uint32_t sb = (uint32_t)__cvta_generic_to_shared(smem);

    const __half *A, *Bh;
    __half* Ch = nullptr;
    float* C = nullptr;
    if (MODE == 0) {
        if (blockIdx.z == 0) { A = g_kh; Bh = g_Wkh; Ch = g_Kph; }
        else                 { A = g_vh; Bh = g_Wvh; Ch = g_Vph; }
    } else if (MODE == 1) {
        A = g_qh; Bh = g_Wqh;
    } else {
        A = g_Yth; Bh = g_Woh; C = Cout;
    }

    const int tid = threadIdx.x;
    const int wid = tid >> 5, lane = tid & 31;
    const int rowBase = blockIdx.y * 128;
    const int colBase = blockIdx.x * 256;

    // 16 warps: 2 (M) x 8 (N); warp tile 64x32
    const int warpM = (wid >> 3) * 64;
    const int warpN = (wid & 7) * 32;

    const int aRowL = warpM + (lane & 15);
    const int aColL = (lane >> 4) * 8;
    const int bRowL = warpN + ((lane >> 4) << 3) + (lane & 7);
    const int bColL = ((lane >> 3) & 1) * 8;

    float acc[4][4][4];
#pragma unroll
    for (int m = 0; m < 4; m++)
#pragma unroll
        for (int n = 0; n < 4; n++)
#pragma unroll
            for (int r = 0; r < 4; r++) acc[m][n][r] = 0.0f;

    auto fill_stage = [&](int buf, int k0) {
        const uint32_t stg = sb + buf * STAGE_B;
        {   // A: 512 16B-chunks, one per thread
            const int r = tid >> 2, c = tid & 3;
            const uint32_t so = (uint32_t)(r * (LDS * 2) + c * 16);
            cp16(stg + so, A + (size_t)(rowBase + r) * KD + k0 + c * 8);
        }
#pragma unroll
        for (int i = 0; i < 2; i++) {  // B: 1024 chunks, two per thread
            const int ch = tid + i * 512;
            const int r = ch >> 2, c = ch & 3;
            const uint32_t so = (uint32_t)(r * (LDS * 2) + c * 16);
            cp16(stg + A_T + so, Bh + (size_t)(colBase + r) * KD + k0 + c * 8);
        }
        cp_commit();
    };

    fill_stage(0, 0);
    fill_stage(1, BK);

    for (int kt = 0; kt < NT; kt++) {
        if (kt < NT - 1) cp_wait<1>(); else cp_wait<0>();
        __syncthreads();

        if (kt + 2 < NT) fill_stage((kt + 2) % NSTAGE, (kt + 2) * BK);

        const uint32_t stg = sb + (kt % NSTAGE) * STAGE_B;
        const uint32_t sA = stg;
        const uint32_t sB = stg + A_T;

#pragma unroll
        for (int s = 0; s < 2; s++) {   // two k16 sub-steps per BK=32
            uint32_t a[4][4], b[4][2];
#pragma unroll
            for (int p = 0; p < 2; p++) {
                const uint32_t off =
                    (uint32_t)(((bRowL + p * 16) * LDS + s * 16 + bColL) * 2);
                ldsm_x4(b[2 * p][0], b[2 * p][1], b[2 * p + 1][0], b[2 * p + 1][1], sB + off);
            }
#pragma unroll
            for (int mf = 0; mf < 4; mf++) {
                const uint32_t off =
                    (uint32_t)(((aRowL + mf * 16) * LDS + s * 16 + aColL) * 2);
                ldsm_x4(a[mf][0], a[mf][1], a[mf][2], a[mf][3], sA + off);
            }
#pragma unroll
            for (int m = 0; m < 4; m++)
#pragma unroll
                for (int n = 0; n < 4; n++)
                    mma_f16(acc[m][n], a[m], b[n]);
        }
        __syncthreads();
    }

    // ---------------- epilogue ----------------
    const int er = rowBase + warpM + (lane >> 2);
    const int ec = colBase + warpN + (lane & 3) * 2;

    if (MODE == 1) {
        // ratio = num/den for this tile's 256 columns (batch uniform per CTA)
        float* snd = (float*)smem;
        const int b = rowBase >> 11;
        if (tid < 256)
            snd[tid] = g_num[b * DD + colBase + tid] / g_den[b * DD + colBase + tid];
        __syncthreads();
#pragma unroll
        for (int m = 0; m < 4; m++)
#pragma unroll
            for (int n = 0; n < 4; n++) {
                const int cl = (ec - colBase) + n * 8;
                const float r0 = snd[cl], r1 = snd[cl + 1];
#pragma unroll
                for (int h = 0; h < 2; h++) {
                    const int r = er + m * 16 + h * 8;
                    float y0 = r0 / (1.0f + __expf(-acc[m][n][h * 2]));
                    float y1 = r1 / (1.0f + __expf(-acc[m][n][h * 2 + 1]));
                    *(__half2*)(g_Yth + (size_t)r * DD + colBase + cl) =
                        __floats2half2_rn(y0, y1);
                }
            }
    } else if (MODE == 0) {
#pragma unroll
        for (int m = 0; m < 4; m++)
#pragma unroll
            for (int n = 0; n < 4; n++) {
                const int c = ec + n * 8;
#pragma unroll
                for (int h = 0; h < 2; h++) {
                    const int r = er + m * 16 + h * 8;
                    *(__half2*)(Ch + (size_t)r * DD + c) =
                        __floats2half2_rn(acc[m][n][h * 2], acc[m][n][h * 2 + 1]);
                }
            }
    } else {
#pragma unroll
        for (int m = 0; m < 4; m++)
#pragma unroll
            for (int n = 0; n < 4; n++) {
                const int c = ec + n * 8;
#pragma unroll
                for (int h = 0; h < 2; h++) {
                    const int r = er + m * 16 + h * 8;
                    *(float2*)(C + (size_t)r * DD + c) =
                        make_float2(acc[m][n][h * 2], acc[m][n][h * 2 + 1]);
                }
            }
    }
}

// ---------------- num/den reduction (fp16 inputs) ----------------
// grid = (DD/128, TT/16) = (8, 128); block = 128 threads
__global__ __launch_bounds__(128) void reduce_kernel() {
    const int d  = blockIdx.x * 128 + threadIdx.x;
    const int t0 = blockIdx.y * 16;

    float num0 = 0.f, num1 = 0.f, num2 = 0.f, num3 = 0.f;
    float den0 = 0.f, den1 = 0.f, den2 = 0.f, den3 = 0.f;

#pragma unroll 4
    for (int t = t0; t < t0 + 16; t++) {
        const size_t off = (size_t)t * DD + d;
        float k0 = __half2float(g_Kph[off + (size_t)0 * TT * DD]);
        float k1 = __half2float(g_Kph[off + (size_t)1 * TT * DD]);
        float k2 = __half2float(g_Kph[off + (size_t)2 * TT * DD]);
        float k3 = __half2float(g_Kph[off + (size_t)3 * TT * DD]);
        float m = fmaxf(fmaxf(k0, k1), fmaxf(k2, k3));
        float e0 = __expf(k0 - m);
        float e1 = __expf(k1 - m);
        float e2 = __expf(k2 - m);
        float e3 = __expf(k3 - m);
        float v0 = __half2float(g_Vph[off + (size_t)0 * TT * DD]);
        float v1 = __half2float(g_Vph[off + (size_t)1 * TT * DD]);
        float v2 = __half2float(g_Vph[off + (size_t)2 * TT * DD]);
        float v3 = __half2float(g_Vph[off + (size_t)3 * TT * DD]);
        num0 = fmaf(e0, v0, num0);  den0 += e0;
        num1 = fmaf(e1, v1, num1);  den1 += e1;
        num2 = fmaf(e2, v2, num2);  den2 += e2;
        num3 = fmaf(e3, v3, num3);  den3 += e3;
    }

    atomicAdd(&g_num[0 * DD + d], num0);
    atomicAdd(&g_num[1 * DD + d], num1);
    atomicAdd(&g_num[2 * DD + d], num2);
    atomicAdd(&g_num[3 * DD + d], num3);
    atomicAdd(&g_den[0 * DD + d], den0);
    atomicAdd(&g_den[1 * DD + d], den1);
    atomicAdd(&g_den[2 * DD + d], den2);
    atomicAdd(&g_den[3 * DD + d], den3);
}

// ---------------------------------------------------------------------------
extern "C" void kernel_launch(void* const* d_in, const int* in_sizes, int n_in,
                              void* d_out, int out_size) {
    const float* q  = (const float*)d_in[0];
    const float* k  = (const float*)d_in[1];
    const float* v  = (const float*)d_in[2];
    const float* Wq = (const float*)d_in[3];
    const float* Wk = (const float*)d_in[4];
    const float* Wv = (const float*)d_in[5];
    const float* Wo = (const float*)d_in[6];
    // d_in[7] = W_bias: provably unused (exp(pos_bias - pos_bias) == 1)
    float* out = (float*)d_out;

    cudaFuncSetAttribute(hgemm<0>, cudaFuncAttributeMaxDynamicSharedMemorySize, SMEM_TOTAL);
    cudaFuncSetAttribute(hgemm<1>, cudaFuncAttributeMaxDynamicSharedMemorySize, SMEM_TOTAL);
    cudaFuncSetAttribute(hgemm<2>, cudaFuncAttributeMaxDynamicSharedMemorySize, SMEM_TOTAL);

    // all converts + num/den zeroing in one launch
    convert_all<<<TOT_CH / 256, 256>>>(q, k, v, Wq, Wk, Wv, Wo);

    // K, V projections (merged launch) -> fp16 Kph/Vph
    dim3 kvGrid(DD / 256, MTOT / 128, 2);   // (4, 64, 2)
    hgemm<0><<<kvGrid, 512, SMEM_TOTAL>>>(nullptr);

    // num/den over Kph, Vph
    dim3 redGrid(DD / 128, TT / 16);        // (8, 128)
    reduce_kernel<<<redGrid, 128>>>();

    // Q projection + fused sigmoid*num/den epilogue -> Yt (fp16)
    dim3 qGrid(DD / 256, MTOT / 128);       // (4, 64)
    hgemm<1><<<qGrid, 512, SMEM_TOTAL>>>(nullptr);

    // out = Yt @ Wo^T
    hgemm<2><<<qGrid, 512, SMEM_TOTAL>>>(out);
}

// round 9
// speedup vs baseline: 6.8030x; 1.1928x over previous
#include <cuda_runtime.h>
#include <cuda_fp16.h>
#include <cstdint>

// AFT-Full simplified: exp_pos_bias == 1  =>  num/den are per-(b,d) sums over t.
// out = ( sigmoid(q@WqT) * num/den ) @ WoT
// GEMMs: legacy mma.sync fp16, single-term. This round: 128x128 tiles,
// 256 threads, 2 CTAs/SM (register-capped) for 32 warps/SM latency hiding.

#define BB 4
#define TT 2048
#define DD 1024
#define MTOT (BB * TT)   // 8192
#define KD 1024

// ---------------- scratch (static device globals) ----------------
__device__ __half g_qh[MTOT * KD];
__device__ __half g_kh[MTOT * KD];
__device__ __half g_vh[MTOT * KD];
__device__ __half g_Wqh[DD * KD], g_Wkh[DD * KD], g_Wvh[DD * KD], g_Woh[DD * KD];
__device__ __half g_Yth[MTOT * DD];
__device__ __half g_Kph[MTOT * DD];
__device__ __half g_Vph[MTOT * DD];
__device__ float g_num[BB * DD];
__device__ float g_den[BB * DD];

// ---------------- merged fp32 -> fp16 convert, all 7 tensors ----------------
constexpr int ACT_CH = MTOT * KD / 16;   // 524288 chunks of 16 floats
constexpr int W_CH   = DD * KD / 16;     // 65536
constexpr int TOT_CH = 3 * ACT_CH + 4 * W_CH;

__global__ __launch_bounds__(256) void convert_all(
    const float* __restrict__ q, const float* __restrict__ k, const float* __restrict__ v,
    const float* __restrict__ wq, const float* __restrict__ wk,
    const float* __restrict__ wv, const float* __restrict__ wo)
{
    const int i = blockIdx.x * blockDim.x + threadIdx.x;

    if (i < BB * DD) { g_num[i] = 0.0f; g_den[i] = 0.0f; }

    const float* src;
    __half* dst;
    size_t off;
    if (i < ACT_CH)              { src = q;  dst = g_qh;  off = i; }
    else if (i < 2 * ACT_CH)     { src = k;  dst = g_kh;  off = i - ACT_CH; }
    else if (i < 3 * ACT_CH)     { src = v;  dst = g_vh;  off = i - 2 * ACT_CH; }
    else {
        int w = i - 3 * ACT_CH;
        int t = w >> 16;
        off = w & 65535;
        if (t == 0)      { src = wq; dst = g_Wqh; }
        else if (t == 1) { src = wk; dst = g_Wkh; }
        else if (t == 2) { src = wv; dst = g_Wvh; }
        else             { src = wo; dst = g_Woh; }
    }

    const float4* s4 = (const float4*)(src) + off * 4;
    float4 x0 = s4[0], x1 = s4[1], x2 = s4[2], x3 = s4[3];
    float xs[16] = {x0.x, x0.y, x0.z, x0.w, x1.x, x1.y, x1.z, x1.w,
                    x2.x, x2.y, x2.z, x2.w, x3.x, x3.y, x3.z, x3.w};
    __half h[16];
#pragma unroll
    for (int j = 0; j < 16; j++) h[j] = __float2half(xs[j]);
    uint4* d4 = (uint4*)(dst + off * 16);
    d4[0] = *(uint4*)(h);
    d4[1] = *(uint4*)(h + 8);
}

// ---------------- PTX helpers ----------------
__device__ __forceinline__ void ldsm_x4(uint32_t& r0, uint32_t& r1, uint32_t& r2, uint32_t& r3, uint32_t addr) {
    asm volatile("ldmatrix.sync.aligned.m8n8.x4.shared.b16 {%0,%1,%2,%3}, [%4];"
                 : "=r"(r0), "=r"(r1), "=r"(r2), "=r"(r3) : "r"(addr));
}
__device__ __forceinline__ void mma_f16(float* d, const uint32_t* a, const uint32_t* b) {
    asm volatile("mma.sync.aligned.m16n8k16.row.col.f32.f16.f16.f32 "
                 "{%0,%1,%2,%3}, {%4,%5,%6,%7}, {%8,%9}, {%0,%1,%2,%3};"
                 : "+f"(d[0]), "+f"(d[1]), "+f"(d[2]), "+f"(d[3])
                 : "r"(a[0]), "r"(a[1]), "r"(a[2]), "r"(a[3]), "r"(b[0]), "r"(b[1]));
}
__device__ __forceinline__ void cp16(uint32_t s, const void* g) {
    asm volatile("cp.async.cg.shared.global [%0], [%1], 16;" :: "r"(s), "l"(g));
}
__device__ __forceinline__ void cp_commit() {
    asm volatile("cp.async.commit_group;" ::: "memory");
}
template <int N>
__device__ __forceinline__ void cp_wait() {
    asm volatile("cp.async.wait_group %0;" :: "n"(N) : "memory");
}

// ---------------- tensor-core GEMM: C[M,N] = A[M,K] @ B[N,K]^T ----------------
// BM=BN=128, BK=32, 3-stage cp.async, 256 threads (8 warps 2x4, warp 64x32),
// 2 CTAs/SM. MODE 0: K/V merged -> fp16. MODE 1: Q + fused sigmoid*ratio -> Yt.
// MODE 2: out = Yt @ Wo^T -> fp32.
constexpr int BK = 32;
constexpr int NT = KD / BK;              // 32 k-tiles
constexpr int LDS = BK + 8;              // 40 halfs = 80 B row stride
constexpr int A_T = 128 * LDS * 2;       // 10240 B
constexpr int B_T = 128 * LDS * 2;       // 10240 B
constexpr int STAGE_B = A_T + B_T;       // 20480 B
constexpr int NSTAGE = 3;
constexpr int SMEM_TOTAL = NSTAGE * STAGE_B;  // 61440 B

template <int MODE>
__global__ __launch_bounds__(256, 2) void hgemm(float* __restrict__ Cout)
{
    extern __shared__ char smem[];
    const uint32_t sb = (uint32_t)__cvta_generic_to_shared(smem);

    const __half *A, *Bh;
    __half* Ch = nullptr;
    float* C = nullptr;
    if (MODE == 0) {
        if (blockIdx.z == 0) { A = g_kh; Bh = g_Wkh; Ch = g_Kph; }
        else                 { A = g_vh; Bh = g_Wvh; Ch = g_Vph; }
    } else if (MODE == 1) {
        A = g_qh; Bh = g_Wqh;
    } else {
        A = g_Yth; Bh = g_Woh; C = Cout;
    }

    const int tid = threadIdx.x;
    const int wid = tid >> 5, lane = tid & 31;
    const int rowBase = blockIdx.y * 128;
    const int colBase = blockIdx.x * 128;

    // 8 warps: 2 (M) x 4 (N); warp tile 64x32
    const int warpM = (wid >> 2) * 64;
    const int warpN = (wid & 3) * 32;

    const int aRowL = warpM + (lane & 15);
    const int aColL = (lane >> 4) * 8;
    const int bRowL = warpN + ((lane >> 4) << 3) + (lane & 7);
    const int bColL = ((lane >> 3) & 1) * 8;

    float acc[4][4][4];
#pragma unroll
    for (int m = 0; m < 4; m++)
#pragma unroll
        for (int n = 0; n < 4; n++)
#pragma unroll
            for (int r = 0; r < 4; r++) acc[m][n][r] = 0.0f;

    auto fill_stage = [&](int buf, int k0) {
        const uint32_t stg = sb + buf * STAGE_B;
#pragma unroll
        for (int i = 0; i < 2; i++) {   // A: 512 chunks, 2/thread
            const int ch = tid + i * 256;
            const int r = ch >> 2, c = ch & 3;
            const uint32_t so = (uint32_t)(r * (LDS * 2) + c * 16);
            cp16(stg + so, A + (size_t)(rowBase + r) * KD + k0 + c * 8);
        }
#pragma unroll
        for (int i = 0; i < 2; i++) {   // B: 512 chunks, 2/thread
            const int ch = tid + i * 256;
            const int r = ch >> 2, c = ch & 3;
            const uint32_t so = (uint32_t)(r * (LDS * 2) + c * 16);
            cp16(stg + A_T + so, Bh + (size_t)(colBase + r) * KD + k0 + c * 8);
        }
        cp_commit();
    };

    fill_stage(0, 0);
    fill_stage(1, BK);

    for (int kt = 0; kt < NT; kt++) {
        if (kt < NT - 1) cp_wait<1>(); else cp_wait<0>();
        __syncthreads();

        if (kt + 2 < NT) fill_stage((kt + 2) % NSTAGE, (kt + 2) * BK);

        const uint32_t stg = sb + (kt % NSTAGE) * STAGE_B;
        const uint32_t sA = stg;
        const uint32_t sB = stg + A_T;

#pragma unroll
        for (int s = 0; s < 2; s++) {   // two k16 sub-steps per BK=32
            uint32_t a[4][4], b[4][2];
#pragma unroll
            for (int p = 0; p < 2; p++) {
                const uint32_t off =
                    (uint32_t)(((bRowL + p * 16) * LDS + s * 16 + bColL) * 2);
                ldsm_x4(b[2 * p][0], b[2 * p][1], b[2 * p + 1][0], b[2 * p + 1][1], sB + off);
            }
#pragma unroll
            for (int mf = 0; mf < 4; mf++) {
                const uint32_t off =
                    (uint32_t)(((aRowL + mf * 16) * LDS + s * 16 + aColL) * 2);
                ldsm_x4(a[mf][0], a[mf][1], a[mf][2], a[mf][3], sA + off);
            }
#pragma unroll
            for (int m = 0; m < 4; m++)
#pragma unroll
                for (int n = 0; n < 4; n++)
                    mma_f16(acc[m][n], a[m], b[n]);
        }
        __syncthreads();
    }

    // ---------------- epilogue ----------------
    const int er = rowBase + warpM + (lane >> 2);
    const int ec = colBase + warpN + (lane & 3) * 2;

    if (MODE == 1) {
        float* snd = (float*)smem;
        const int b = rowBase >> 11;
        if (tid < 128)
            snd[tid] = g_num[b * DD + colBase + tid] / g_den[b * DD + colBase + tid];
        __syncthreads();
#pragma unroll
        for (int m = 0; m < 4; m++)
#pragma unroll
            for (int n = 0; n < 4; n++) {
                const int cl = (ec - colBase) + n * 8;
                const float r0 = snd[cl], r1 = snd[cl + 1];
#pragma unroll
                for (int h = 0; h < 2; h++) {
                    const int r = er + m * 16 + h * 8;
                    float y0 = r0 / (1.0f + __expf(-acc[m][n][h * 2]));
                    float y1 = r1 / (1.0f + __expf(-acc[m][n][h * 2 + 1]));
                    *(__half2*)(g_Yth + (size_t)r * DD + colBase + cl) =
                        __floats2half2_rn(y0, y1);
                }
            }
    } else if (MODE == 0) {
#pragma unroll
        for (int m = 0; m < 4; m++)
#pragma unroll
            for (int n = 0; n < 4; n++) {
                const int c = ec + n * 8;
#pragma unroll
                for (int h = 0; h < 2; h++) {
                    const int r = er + m * 16 + h * 8;
                    *(__half2*)(Ch + (size_t)r * DD + c) =
                        __floats2half2_rn(acc[m][n][h * 2], acc[m][n][h * 2 + 1]);
                }
            }
    } else {
#pragma unroll
        for (int m = 0; m < 4; m++)
#pragma unroll
            for (int n = 0; n < 4; n++) {
                const int c = ec + n * 8;
#pragma unroll
                for (int h = 0; h < 2; h++) {
                    const int r = er + m * 16 + h * 8;
                    *(float2*)(C + (size_t)r * DD + c) =
                        make_float2(acc[m][n][h * 2], acc[m][n][h * 2 + 1]);
                }
            }
    }
}

// ---------------- num/den reduction (fp16 inputs) ----------------
__global__ __launch_bounds__(128) void reduce_kernel() {
    const int d  = blockIdx.x * 128 + threadIdx.x;
    const int t0 = blockIdx.y * 16;

    float num0 = 0.f, num1 = 0.f, num2 = 0.f, num3 = 0.f;
    float den0 = 0.f, den1 = 0.f, den2 = 0.f, den3 = 0.f;

#pragma unroll 4
    for (int t = t0; t < t0 + 16; t++) {
        const size_t off = (size_t)t * DD + d;
        float k0 = __half2float(g_Kph[off + (size_t)0 * TT * DD]);
        float k1 = __half2float(g_Kph[off + (size_t)1 * TT * DD]);
        float k2 = __half2float(g_Kph[off + (size_t)2 * TT * DD]);
        float k3 = __half2float(g_Kph[off + (size_t)3 * TT * DD]);
        float m = fmaxf(fmaxf(k0, k1), fmaxf(k2, k3));
        float e0 = __expf(k0 - m);
        float e1 = __expf(k1 - m);
        float e2 = __expf(k2 - m);
        float e3 = __expf(k3 - m);
        float v0 = __half2float(g_Vph[off + (size_t)0 * TT * DD]);
        float v1 = __half2float(g_Vph[off + (size_t)1 * TT * DD]);
        float v2 = __half2float(g_Vph[off + (size_t)2 * TT * DD]);
        float v3 = __half2float(g_Vph[off + (size_t)3 * TT * DD]);
        num0 = fmaf(e0, v0, num0);  den0 += e0;
        num1 = fmaf(e1, v1, num1);  den1 += e1;
        num2 = fmaf(e2, v2, num2);  den2 += e2;
        num3 = fmaf(e3, v3, num3);  den3 += e3;
    }

    atomicAdd(&g_num[0 * DD + d], num0);
    atomicAdd(&g_num[1 * DD + d], num1);
    atomicAdd(&g_num[2 * DD + d], num2);
    atomicAdd(&g_num[3 * DD + d], num3);
    atomicAdd(&g_den[0 * DD + d], den0);
    atomicAdd(&g_den[1 * DD + d], den1);
    atomicAdd(&g_den[2 * DD + d], den2);
    atomicAdd(&g_den[3 * DD + d], den3);
}

// ---------------------------------------------------------------------------
extern "C" void kernel_launch(void* const* d_in, const int* in_sizes, int n_in,
                              void* d_out, int out_size) {
    const float* q  = (const float*)d_in[0];
    const float* k  = (const float*)d_in[1];
    const float* v  = (const float*)d_in[2];
    const float* Wq = (const float*)d_in[3];
    const float* Wk = (const float*)d_in[4];
    const float* Wv = (const float*)d_in[5];
    const float* Wo = (const float*)d_in[6];
    // d_in[7] = W_bias: provably unused (exp(pos_bias - pos_bias) == 1)
    float* out = (float*)d_out;

    cudaFuncSetAttribute(hgemm<0>, cudaFuncAttributeMaxDynamicSharedMemorySize, SMEM_TOTAL);
    cudaFuncSetAttribute(hgemm<1>, cudaFuncAttributeMaxDynamicSharedMemorySize, SMEM_TOTAL);
    cudaFuncSetAttribute(hgemm<2>, cudaFuncAttributeMaxDynamicSharedMemorySize, SMEM_TOTAL);

    // all converts + num/den zeroing in one launch
    convert_all<<<TOT_CH / 256, 256>>>(q, k, v, Wq, Wk, Wv, Wo);

    // K, V projections (merged launch) -> fp16 Kph/Vph
    dim3 kvGrid(DD / 128, MTOT / 128, 2);   // (8, 64, 2)
    hgemm<0><<<kvGrid, 256, SMEM_TOTAL>>>(nullptr);

    // num/den over Kph, Vph
    dim3 redGrid(DD / 128, TT / 16);        // (8, 128)
    reduce_kernel<<<redGrid, 128>>>();

    // Q projection + fused sigmoid*num/den epilogue -> Yt (fp16)
    dim3 qGrid(DD / 128, MTOT / 128);       // (8, 64)
    hgemm<1><<<qGrid, 256, SMEM_TOTAL>>>(nullptr);

    // out = Yt @ Wo^T
    hgemm<2><<<qGrid, 256, SMEM_TOTAL>>>(out);
}

// round 10
// speedup vs baseline: 8.1965x; 1.2048x over previous
#include <cuda_runtime.h>
#include <cuda_fp16.h>
#include <cstdint>

// AFT-Full simplified: exp_pos_bias == 1  =>  num/den are per-(b,d) sums over t.
// out = ( sigmoid(q@WqT) * num/den ) @ WoT
// GEMMs: legacy mma.sync fp16 single-term, 128x128 tiles, 256 thr, 2 CTAs/SM.
// This round: BK=64 (half the barriers) + XOR-swizzled smem (no padding,
// 96KB/CTA so 2 CTAs still fit).

#define BB 4
#define TT 2048
#define DD 1024
#define MTOT (BB * TT)   // 8192
#define KD 1024

// ---------------- scratch (static device globals) ----------------
__device__ __half g_qh[MTOT * KD];
__device__ __half g_kh[MTOT * KD];
__device__ __half g_vh[MTOT * KD];
__device__ __half g_Wqh[DD * KD], g_Wkh[DD * KD], g_Wvh[DD * KD], g_Woh[DD * KD];
__device__ __half g_Yth[MTOT * DD];
__device__ __half g_Kph[MTOT * DD];
__device__ __half g_Vph[MTOT * DD];
__device__ float g_num[BB * DD];
__device__ float g_den[BB * DD];

// ---------------- merged fp32 -> fp16 convert, all 7 tensors ----------------
constexpr int ACT_CH = MTOT * KD / 16;   // 524288 chunks of 16 floats
constexpr int W_CH   = DD * KD / 16;     // 65536
constexpr int TOT_CH = 3 * ACT_CH + 4 * W_CH;

__global__ __launch_bounds__(256) void convert_all(
    const float* __restrict__ q, const float* __restrict__ k, const float* __restrict__ v,
    const float* __restrict__ wq, const float* __restrict__ wk,
    const float* __restrict__ wv, const float* __restrict__ wo)
{
    const int i = blockIdx.x * blockDim.x + threadIdx.x;

    if (i < BB * DD) { g_num[i] = 0.0f; g_den[i] = 0.0f; }

    const float* src;
    __half* dst;
    size_t off;
    if (i < ACT_CH)              { src = q;  dst = g_qh;  off = i; }
    else if (i < 2 * ACT_CH)     { src = k;  dst = g_kh;  off = i - ACT_CH; }
    else if (i < 3 * ACT_CH)     { src = v;  dst = g_vh;  off = i - 2 * ACT_CH; }
    else {
        int w = i - 3 * ACT_CH;
        int t = w >> 16;
        off = w & 65535;
        if (t == 0)      { src = wq; dst = g_Wqh; }
        else if (t == 1) { src = wk; dst = g_Wkh; }
        else if (t == 2) { src = wv; dst = g_Wvh; }
        else             { src = wo; dst = g_Woh; }
    }

    const float4* s4 = (const float4*)(src) + off * 4;
    float4 x0 = s4[0], x1 = s4[1], x2 = s4[2], x3 = s4[3];
    float xs[16] = {x0.x, x0.y, x0.z, x0.w, x1.x, x1.y, x1.z, x1.w,
                    x2.x, x2.y, x2.z, x2.w, x3.x, x3.y, x3.z, x3.w};
    __half h[16];
#pragma unroll
    for (int j = 0; j < 16; j++) h[j] = __float2half(xs[j]);
    uint4* d4 = (uint4*)(dst + off * 16);
    d4[0] = *(uint4*)(h);
    d4[1] = *(uint4*)(h + 8);
}

// ---------------- PTX helpers ----------------
__device__ __forceinline__ void ldsm_x4(uint32_t& r0, uint32_t& r1, uint32_t& r2, uint32_t& r3, uint32_t addr) {
    asm volatile("ldmatrix.sync.aligned.m8n8.x4.shared.b16 {%0,%1,%2,%3}, [%4];"
                 : "=r"(r0), "=r"(r1), "=r"(r2), "=r"(r3) : "r"(addr));
}
__device__ __forceinline__ void mma_f16(float* d, const uint32_t* a, const uint32_t* b) {
    asm volatile("mma.sync.aligned.m16n8k16.row.col.f32.f16.f16.f32 "
                 "{%0,%1,%2,%3}, {%4,%5,%6,%7}, {%8,%9}, {%0,%1,%2,%3};"
                 : "+f"(d[0]), "+f"(d[1]), "+f"(d[2]), "+f"(d[3])
                 : "r"(a[0]), "r"(a[1]), "r"(a[2]), "r"(a[3]), "r"(b[0]), "r"(b[1]));
}
__device__ __forceinline__ void cp16(uint32_t s, const void* g) {
    asm volatile("cp.async.cg.shared.global [%0], [%1], 16;" :: "r"(s), "l"(g));
}
__device__ __forceinline__ void cp_commit() {
    asm volatile("cp.async.commit_group;" ::: "memory");
}
template <int N>
__device__ __forceinline__ void cp_wait() {
    asm volatile("cp.async.wait_group %0;" :: "n"(N) : "memory");
}

// ---------------- tensor-core GEMM: C[M,N] = A[M,K] @ B[N,K]^T ----------------
// BM=BN=128, BK=64, 3-stage cp.async, 256 threads (8 warps 2x4, warp 64x32),
// 2 CTAs/SM. Smem rows are exactly 128 B with Swizzle<3,4,3>:
//   16B-chunk column index c (0..7) stored at (c ^ (row & 7)).
// MODE 0: K/V merged -> fp16. MODE 1: Q + fused sigmoid*ratio -> Yt.
// MODE 2: out = Yt @ Wo^T -> fp32.
constexpr int BK = 64;
constexpr int NT = KD / BK;              // 16 k-tiles
constexpr int A_T = 128 * BK * 2;        // 16384 B
constexpr int STAGE_B = 2 * A_T;         // 32768 B (A then B)
constexpr int NSTAGE = 3;
constexpr int SMEM_TOTAL = NSTAGE * STAGE_B;  // 98304 B

template <int MODE>
__global__ __launch_bounds__(256, 2) void hgemm(float* __restrict__ Cout)
{
    extern __shared__ char smem[];
    const uint32_t sb = (uint32_t)__cvta_generic_to_shared(smem);

    const __half *A, *Bh;
    __half* Ch = nullptr;
    float* C = nullptr;
    if (MODE == 0) {
        if (blockIdx.z == 0) { A = g_kh; Bh = g_Wkh; Ch = g_Kph; }
        else                 { A = g_vh; Bh = g_Wvh; Ch = g_Vph; }
    } else if (MODE == 1) {
        A = g_qh; Bh = g_Wqh;
    } else {
        A = g_Yth; Bh = g_Woh; C = Cout;
    }

    const int tid = threadIdx.x;
    const int wid = tid >> 5, lane = tid & 31;
    const int rowBase = blockIdx.y * 128;
    const int colBase = blockIdx.x * 128;

    // 8 warps: 2 (M) x 4 (N); warp tile 64x32
    const int warpM = (wid >> 2) * 64;
    const int warpN = (wid & 3) * 32;

    // per-lane ldmatrix rows and 16B-column bases
    const int aRowL = warpM + (lane & 15);
    const int aC16  = (lane >> 4);            // 0 or 1 (col 0 / col 8 halfs)
    const int bRowL = warpN + ((lane >> 4) << 3) + (lane & 7);
    const int bC16  = ((lane >> 3) & 1);

    float acc[4][4][4];
#pragma unroll
    for (int m = 0; m < 4; m++)
#pragma unroll
        for (int n = 0; n < 4; n++)
#pragma unroll
            for (int r = 0; r < 4; r++) acc[m][n][r] = 0.0f;

    auto fill_stage = [&](int buf, int k0) {
        const uint32_t stg = sb + buf * STAGE_B;
#pragma unroll
        for (int i = 0; i < 4; i++) {   // A: 1024 chunks of 16B, 4/thread
            const int ch = tid + i * 256;
            const int r = ch >> 3, c = ch & 7;
            const uint32_t so = (uint32_t)(r * 128 + ((c ^ (r & 7)) * 16));
            cp16(stg + so, A + (size_t)(rowBase + r) * KD + k0 + c * 8);
        }
#pragma unroll
        for (int i = 0; i < 4; i++) {   // B: 1024 chunks, 4/thread
            const int ch = tid + i * 256;
            const int r = ch >> 3, c = ch & 7;
            const uint32_t so = (uint32_t)(r * 128 + ((c ^ (r & 7)) * 16));
            cp16(stg + A_T + so, Bh + (size_t)(colBase + r) * KD + k0 + c * 8);
        }
        cp_commit();
    };

    fill_stage(0, 0);
    fill_stage(1, BK);

    for (int kt = 0; kt < NT; kt++) {
        if (kt < NT - 1) cp_wait<1>(); else cp_wait<0>();
        __syncthreads();

        if (kt + 2 < NT) fill_stage((kt + 2) % NSTAGE, (kt + 2) * BK);

        const uint32_t stg = sb + (kt % NSTAGE) * STAGE_B;
        const uint32_t sA = stg;
        const uint32_t sB = stg + A_T;

#pragma unroll
        for (int s = 0; s < 4; s++) {   // four k16 sub-steps per BK=64
            uint32_t a[4][4], b[4][2];
#pragma unroll
            for (int p = 0; p < 2; p++) {
                const int row = bRowL + p * 16;
                const int c16 = (s * 2 + bC16) ^ (row & 7);
                const uint32_t addr = sB + (uint32_t)(row * 128 + c16 * 16);
                ldsm_x4(b[2 * p][0], b[2 * p][1], b[2 * p + 1][0], b[2 * p + 1][1], addr);
            }
#pragma unroll
            for (int mf = 0; mf < 4; mf++) {
                const int row = aRowL + mf * 16;
                const int c16 = (s * 2 + aC16) ^ (row & 7);
                const uint32_t addr = sA + (uint32_t)(row * 128 + c16 * 16);
                ldsm_x4(a[mf][0], a[mf][1], a[mf][2], a[mf][3], addr);
            }
#pragma unroll
            for (int m = 0; m < 4; m++)
#pragma unroll
                for (int n = 0; n < 4; n++)
                    mma_f16(acc[m][n], a[m], b[n]);
        }
        __syncthreads();
    }

    // ---------------- epilogue ----------------
    const int er = rowBase + warpM + (lane >> 2);
    const int ec = colBase + warpN + (lane & 3) * 2;

    if (MODE == 1) {
        float* snd = (float*)smem;
        const int b = rowBase >> 11;
        if (tid < 128)
            snd[tid] = g_num[b * DD + colBase + tid] / g_den[b * DD + colBase + tid];
        __syncthreads();
#pragma unroll
        for (int m = 0; m < 4; m++)
#pragma unroll
            for (int n = 0; n < 4; n++) {
                const int cl = (ec - colBase) + n * 8;
                const float r0 = snd[cl], r1 = snd[cl + 1];
#pragma unroll
                for (int h = 0; h < 2; h++) {
                    const int r = er + m * 16 + h * 8;
                    float y0 = r0 / (1.0f + __expf(-acc[m][n][h * 2]));
                    float y1 = r1 / (1.0f + __expf(-acc[m][n][h * 2 + 1]));
                    *(__half2*)(g_Yth + (size_t)r * DD + colBase + cl) =
                        __floats2half2_rn(y0, y1);
                }
            }
    } else if (MODE == 0) {
#pragma unroll
        for (int m = 0; m < 4; m++)
#pragma unroll
            for (int n = 0; n < 4; n++) {
                const int c = ec + n * 8;
#pragma unroll
                for (int h = 0; h < 2; h++) {
                    const int r = er + m * 16 + h * 8;
                    *(__half2*)(Ch + (size_t)r * DD + c) =
                        __floats2half2_rn(acc[m][n][h * 2], acc[m][n][h * 2 + 1]);
                }
            }
    } else {
#pragma unroll
        for (int m = 0; m < 4; m++)
#pragma unroll
            for (int n = 0; n < 4; n++) {
                const int c = ec + n * 8;
#pragma unroll
                for (int h = 0; h < 2; h++) {
                    const int r = er + m * 16 + h * 8;
                    *(float2*)(C + (size_t)r * DD + c) =
                        make_float2(acc[m][n][h * 2], acc[m][n][h * 2 + 1]);
                }
            }
    }
}

// ---------------- num/den reduction (fp16 inputs) ----------------
__global__ __launch_bounds__(128) void reduce_kernel() {
    const int d  = blockIdx.x * 128 + threadIdx.x;
    const int t0 = blockIdx.y * 16;

    float num0 = 0.f, num1 = 0.f, num2 = 0.f, num3 = 0.f;
    float den0 = 0.f, den1 = 0.f, den2 = 0.f, den3 = 0.f;

#pragma unroll 4
    for (int t = t0; t < t0 + 16; t++) {
        const size_t off = (size_t)t * DD + d;
        float k0 = __half2float(g_Kph[off + (size_t)0 * TT * DD]);
        float k1 = __half2float(g_Kph[off + (size_t)1 * TT * DD]);
        float k2 = __half2float(g_Kph[off + (size_t)2 * TT * DD]);
        float k3 = __half2float(g_Kph[off + (size_t)3 * TT * DD]);
        float m = fmaxf(fmaxf(k0, k1), fmaxf(k2, k3));
        float e0 = __expf(k0 - m);
        float e1 = __expf(k1 - m);
        float e2 = __expf(k2 - m);
        float e3 = __expf(k3 - m);
        float v0 = __half2float(g_Vph[off + (size_t)0 * TT * DD]);
        float v1 = __half2float(g_Vph[off + (size_t)1 * TT * DD]);
        float v2 = __half2float(g_Vph[off + (size_t)2 * TT * DD]);
        float v3 = __half2float(g_Vph[off + (size_t)3 * TT * DD]);
        num0 = fmaf(e0, v0, num0);  den0 += e0;
        num1 = fmaf(e1, v1, num1);  den1 += e1;
        num2 = fmaf(e2, v2, num2);  den2 += e2;
        num3 = fmaf(e3, v3, num3);  den3 += e3;
    }

    atomicAdd(&g_num[0 * DD + d], num0);
    atomicAdd(&g_num[1 * DD + d], num1);
    atomicAdd(&g_num[2 * DD + d], num2);
    atomicAdd(&g_num[3 * DD + d], num3);
    atomicAdd(&g_den[0 * DD + d], den0);
    atomicAdd(&g_den[1 * DD + d], den1);
    atomicAdd(&g_den[2 * DD + d], den2);
    atomicAdd(&g_den[3 * DD + d], den3);
}

// ---------------------------------------------------------------------------
extern "C" void kernel_launch(void* const* d_in, const int* in_sizes, int n_in,
                              void* d_out, int out_size) {
    const float* q  = (const float*)d_in[0];
    const float* k  = (const float*)d_in[1];
    const float* v  = (const float*)d_in[2];
    const float* Wq = (const float*)d_in[3];
    const float* Wk = (const float*)d_in[4];
    const float* Wv = (const float*)d_in[5];
    const float* Wo = (const float*)d_in[6];
    // d_in[7] = W_bias: provably unused (exp(pos_bias - pos_bias) == 1)
    float* out = (float*)d_out;

    cudaFuncSetAttribute(hgemm<0>, cudaFuncAttributeMaxDynamicSharedMemorySize, SMEM_TOTAL);
    cudaFuncSetAttribute(hgemm<1>, cudaFuncAttributeMaxDynamicSharedMemorySize, SMEM_TOTAL);
    cudaFuncSetAttribute(hgemm<2>, cudaFuncAttributeMaxDynamicSharedMemorySize, SMEM_TOTAL);

    // all converts + num/den zeroing in one launch
    convert_all<<<TOT_CH / 256, 256>>>(q, k, v, Wq, Wk, Wv, Wo);

    // K, V projections (merged launch) -> fp16 Kph/Vph
    dim3 kvGrid(DD / 128, MTOT / 128, 2);   // (8, 64, 2)
    hgemm<0><<<kvGrid, 256, SMEM_TOTAL>>>(nullptr);

    // num/den over Kph, Vph
    dim3 redGrid(DD / 128, TT / 16);        // (8, 128)
    reduce_kernel<<<redGrid, 128>>>();

    // Q projection + fused sigmoid*num/den epilogue -> Yt (fp16)
    dim3 qGrid(DD / 128, MTOT / 128);       // (8, 64)
    hgemm<1><<<qGrid, 256, SMEM_TOTAL>>>(nullptr);

    // out = Yt @ Wo^T
    hgemm<2><<<qGrid, 256, SMEM_TOTAL>>>(out);
}